// round 1
// baseline (speedup 1.0000x reference)
#include <cuda_runtime.h>
#include <cuda_bf16.h>
#include <math.h>

// Problem constants
#define BB 4
#define SS 4096
#define DD 128
#define HH 8
#define KK 128
#define MM 256

#define BS   (BB*SS)        // 16384
#define BSH  (BB*SS*HH)     // 131072
#define HK   (HH*KK)        // 1024
#define HM   (HH*MM)        // 2048

// -------- scratch (static device globals; no allocation allowed) --------
__device__ float g_Xn  [BS*DD];
__device__ float g_q   [BS*HK];
__device__ float g_k   [BS*HK];
__device__ float g_v   [BS*HK];
__device__ float g_qp  [BSH*MM];
__device__ float g_kp  [BSH*MM];
__device__ float g_kv  [BB*HH*MM*KK];
__device__ float g_ks  [BB*HH*MM];
__device__ float g_dn  [BSH];
__device__ float g_attn[BS*HK];
__device__ float g_ao  [BS*DD];
__device__ float g_out1[BS*DD];
__device__ float g_tA  [BS*DD];
__device__ float g_tB  [BS*DD];

// ---------------- LayerNorm (eps=1e-3), optional residual+mask ----------------
// out[row,:] = LN(in1[row,:] + in2[row,:]*maskf(row)) * g + b
__global__ void ln_kernel(const float* __restrict__ in1, const float* __restrict__ in2,
                          const int* __restrict__ mask,
                          const float* __restrict__ gamma, const float* __restrict__ beta,
                          float* __restrict__ out)
{
    int row = blockIdx.x;
    int t = threadIdx.x;              // 128 threads, one per feature
    float x = in1[(size_t)row*DD + t];
    if (in2) {
        float mf = mask ? (float)mask[row] : 1.0f;
        x += in2[(size_t)row*DD + t] * mf;
    }
    __shared__ float sm[4];
    float s = x;
    #pragma unroll
    for (int o = 16; o; o >>= 1) s += __shfl_down_sync(0xffffffffu, s, o);
    if ((t & 31) == 0) sm[t >> 5] = s;
    __syncthreads();
    float mu = (sm[0] + sm[1] + sm[2] + sm[3]) * (1.0f/128.0f);
    float d = x - mu;
    float s2 = d * d;
    __syncthreads();
    #pragma unroll
    for (int o = 16; o; o >>= 1) s2 += __shfl_down_sync(0xffffffffu, s2, o);
    if ((t & 31) == 0) sm[t >> 5] = s2;
    __syncthreads();
    float var = (sm[0] + sm[1] + sm[2] + sm[3]) * (1.0f/128.0f);
    out[(size_t)row*DD + t] = d * rsqrtf(var + 1e-3f) * gamma[t] + beta[t];
}

// ---------------- Generic tiled SGEMM, C[M,N] = A[M,Kd] @ op(B) ----------------
// TRANSB: B given as [N,Kd] row-major (used for proj).
// EPI 0: C = (acc + bias[n]) * alpha
// EPI 1: C = elu(acc + bias[n])                     (FFN dense 1)
// EPI 2: C = (elu(acc)+1) * alpha * maskf(row/Hrep) (performer feature map)
template<int EPI, bool TRANSB>
__global__ void gemm_kernel(const float* __restrict__ A, const float* __restrict__ B,
                            float* __restrict__ C, const float* __restrict__ bias,
                            const int* __restrict__ mask, float alpha,
                            int M, int N, int Kd, int Hrep)
{
    __shared__ float As[16][64];
    __shared__ float Bs[16][64];
    int tid = threadIdx.x;
    int tx = tid & 15, ty = tid >> 4;
    int m0 = blockIdx.y * 64, n0 = blockIdx.x * 64;
    float acc[4][4] = {};
    for (int k0 = 0; k0 < Kd; k0 += 16) {
        #pragma unroll
        for (int u = 0; u < 4; u++) {
            int idx = tid*4 + u;
            int r = idx >> 4, kk = idx & 15;
            As[kk][r] = A[(size_t)(m0 + r) * Kd + k0 + kk];
        }
        #pragma unroll
        for (int u = 0; u < 4; u++) {
            int idx = tid*4 + u;
            int kk = idx >> 6, c = idx & 63;
            Bs[kk][c] = TRANSB ? B[(size_t)(n0 + c) * Kd + k0 + kk]
                               : B[(size_t)(k0 + kk) * N + n0 + c];
        }
        __syncthreads();
        #pragma unroll
        for (int kk = 0; kk < 16; kk++) {
            float a[4], b[4];
            #pragma unroll
            for (int i = 0; i < 4; i++) a[i] = As[kk][ty*4 + i];
            #pragma unroll
            for (int j = 0; j < 4; j++) b[j] = Bs[kk][tx*4 + j];
            #pragma unroll
            for (int i = 0; i < 4; i++)
                #pragma unroll
                for (int j = 0; j < 4; j++)
                    acc[i][j] = fmaf(a[i], b[j], acc[i][j]);
        }
        __syncthreads();
    }
    #pragma unroll
    for (int i = 0; i < 4; i++) {
        int row = m0 + ty*4 + i;
        float mf = 1.0f;
        if (EPI == 2 && mask) mf = (float)mask[row / Hrep];
        #pragma unroll
        for (int j = 0; j < 4; j++) {
            int col = n0 + tx*4 + j;
            float v = acc[i][j];
            if (EPI == 0) {
                if (bias) v += bias[col];
                v *= alpha;
            } else if (EPI == 1) {
                v += bias[col];
                v = v > 0.0f ? v : expm1f(v);
            } else {
                v = v > 0.0f ? v + 1.0f : expf(v);   // elu(x)+1
                v *= alpha * mf;
            }
            C[(size_t)row * N + col] = v;
        }
    }
}

// ---------------- kv[b,h,m,k] = sum_s kp[b,s,h,m] * v[b,s,h,k] ----------------
__global__ void kv_kernel(const float* __restrict__ kp, const float* __restrict__ vv,
                          float* __restrict__ kvout)
{
    int bh = blockIdx.z;
    int b = bh >> 3, h = bh & 7;
    int m0 = blockIdx.y * 64, k0 = blockIdx.x * 64;
    const float* kpb = kp + (size_t)b*SS*HM + (size_t)h*MM;
    const float* vb  = vv + (size_t)b*SS*HK + (size_t)h*KK;
    __shared__ float As[16][64];  // [s][m]
    __shared__ float Bs[16][64];  // [s][k]
    int tid = threadIdx.x;
    int tx = tid & 15, ty = tid >> 4;
    float acc[4][4] = {};
    for (int s0 = 0; s0 < SS; s0 += 16) {
        #pragma unroll
        for (int u = 0; u < 4; u++) {
            int idx = tid*4 + u;
            int ss = idx >> 6, c = idx & 63;
            As[ss][c] = kpb[(size_t)(s0 + ss) * HM + m0 + c];
            Bs[ss][c] = vb [(size_t)(s0 + ss) * HK + k0 + c];
        }
        __syncthreads();
        #pragma unroll
        for (int ss = 0; ss < 16; ss++) {
            float a[4], b[4];
            #pragma unroll
            for (int i = 0; i < 4; i++) a[i] = As[ss][ty*4 + i];
            #pragma unroll
            for (int j = 0; j < 4; j++) b[j] = Bs[ss][tx*4 + j];
            #pragma unroll
            for (int i = 0; i < 4; i++)
                #pragma unroll
                for (int j = 0; j < 4; j++)
                    acc[i][j] = fmaf(a[i], b[j], acc[i][j]);
        }
        __syncthreads();
    }
    #pragma unroll
    for (int i = 0; i < 4; i++)
        #pragma unroll
        for (int j = 0; j < 4; j++)
            kvout[((size_t)bh*MM + m0 + ty*4 + i) * KK + k0 + tx*4 + j] = acc[i][j];
}

// ---------------- ksum[b,h,m] = sum_s kp[b,s,h,m] ----------------
__global__ void ksum_kernel(const float* __restrict__ kp, float* __restrict__ ksum)
{
    int bh = blockIdx.x;
    int b = bh >> 3, h = bh & 7;
    int m = threadIdx.x;  // 256 threads
    const float* kpb = kp + (size_t)b*SS*HM + (size_t)h*MM + m;
    float s = 0.0f;
    for (int ss = 0; ss < SS; ss++) s += kpb[(size_t)ss * HM];
    ksum[bh*MM + m] = s;
}

// ---------------- denom[r] = 1/(qp[r,:]·ksum[b,h,:] + 1e-6), r=(b*S+s)*H+h ----------------
__global__ void denom_kernel(const float* __restrict__ qp, const float* __restrict__ ksum,
                             float* __restrict__ denom)
{
    int warp = threadIdx.x >> 5, lane = threadIdx.x & 31;
    int r = blockIdx.x * 8 + warp;
    const float* q = qp + (size_t)r * MM;
    int b = r / (SS * HH);
    int h = r & 7;
    const float* ks = ksum + (b*HH + h) * MM;
    float s = 0.0f;
    for (int i = lane; i < MM; i += 32) s += q[i] * ks[i];
    #pragma unroll
    for (int o = 16; o; o >>= 1) s += __shfl_down_sync(0xffffffffu, s, o);
    if (lane == 0) denom[r] = 1.0f / (s + 1e-6f);
}

// ---------------- attn[b,s,h,k] = (qp[b,s,h,:] @ kv[b,h,:,:]) * denom ----------------
__global__ void attn_kernel(const float* __restrict__ qp, const float* __restrict__ kvin,
                            const float* __restrict__ denom, float* __restrict__ attn)
{
    int bh = blockIdx.z;
    int b = bh >> 3, h = bh & 7;
    int s0 = blockIdx.y * 64, k0 = blockIdx.x * 64;
    const float* qpb = qp + (size_t)b*SS*HM + (size_t)h*MM;
    const float* kvb = kvin + (size_t)bh*MM*KK;
    __shared__ float As[16][64];  // [m][s]
    __shared__ float Bs[16][64];  // [m][k]
    int tid = threadIdx.x;
    int tx = tid & 15, ty = tid >> 4;
    float acc[4][4] = {};
    for (int mt = 0; mt < MM; mt += 16) {
        #pragma unroll
        for (int u = 0; u < 4; u++) {
            int idx = tid*4 + u;
            int ss = idx >> 4, mm = idx & 15;
            As[mm][ss] = qpb[(size_t)(s0 + ss) * HM + mt + mm];
        }
        #pragma unroll
        for (int u = 0; u < 4; u++) {
            int idx = tid*4 + u;
            int mm = idx >> 6, c = idx & 63;
            Bs[mm][c] = kvb[(size_t)(mt + mm) * KK + k0 + c];
        }
        __syncthreads();
        #pragma unroll
        for (int mm = 0; mm < 16; mm++) {
            float a[4], b2[4];
            #pragma unroll
            for (int i = 0; i < 4; i++) a[i] = As[mm][ty*4 + i];
            #pragma unroll
            for (int j = 0; j < 4; j++) b2[j] = Bs[mm][tx*4 + j];
            #pragma unroll
            for (int i = 0; i < 4; i++)
                #pragma unroll
                for (int j = 0; j < 4; j++)
                    acc[i][j] = fmaf(a[i], b2[j], acc[i][j]);
        }
        __syncthreads();
    }
    #pragma unroll
    for (int i = 0; i < 4; i++) {
        int srow = s0 + ty*4 + i;
        float dn = denom[((size_t)b*SS + srow) * HH + h];
        #pragma unroll
        for (int j = 0; j < 4; j++)
            attn[(((size_t)b*SS + srow) * HH + h) * KK + k0 + tx*4 + j] = acc[i][j] * dn;
    }
}

// ---------------- host-side launch ----------------
static float* sym_addr_f(const void* sym)
{
    void* p = nullptr;
    cudaGetSymbolAddress(&p, sym);
    return (float*)p;
}

extern "C" void kernel_launch(void* const* d_in, const int* in_sizes, int n_in,
                              void* d_out, int out_size)
{
    (void)in_sizes; (void)n_in; (void)out_size;
    const float* Q      = (const float*)d_in[0];
    const float* X      = (const float*)d_in[1];
    const int*   mask   = (const int*)  d_in[2];
    const float* Wq     = (const float*)d_in[3];
    const float* bq     = (const float*)d_in[4];
    const float* Wk     = (const float*)d_in[5];
    const float* bk     = (const float*)d_in[6];
    const float* Wv     = (const float*)d_in[7];
    const float* bv     = (const float*)d_in[8];
    const float* Wo     = (const float*)d_in[9];
    const float* bo     = (const float*)d_in[10];
    const float* proj   = (const float*)d_in[11];
    const float* ln1_g  = (const float*)d_in[12];
    const float* ln1_b  = (const float*)d_in[13];
    const float* ln2_g  = (const float*)d_in[14];
    const float* ln2_b  = (const float*)d_in[15];
    const float* fln0_g = (const float*)d_in[16];
    const float* fln0_b = (const float*)d_in[17];
    const float* f_w0   = (const float*)d_in[18];
    const float* f_b0   = (const float*)d_in[19];
    const float* fln1_g = (const float*)d_in[20];
    const float* fln1_b = (const float*)d_in[21];
    const float* f_w1   = (const float*)d_in[22];
    const float* f_b1   = (const float*)d_in[23];
    float* out = (float*)d_out;

    float* Xn   = sym_addr_f(g_Xn);
    float* q    = sym_addr_f(g_q);
    float* k    = sym_addr_f(g_k);
    float* v    = sym_addr_f(g_v);
    float* qp   = sym_addr_f(g_qp);
    float* kp   = sym_addr_f(g_kp);
    float* kv   = sym_addr_f(g_kv);
    float* ks   = sym_addr_f(g_ks);
    float* dn   = sym_addr_f(g_dn);
    float* attn = sym_addr_f(g_attn);
    float* ao   = sym_addr_f(g_ao);
    float* out1 = sym_addr_f(g_out1);
    float* tA   = sym_addr_f(g_tA);
    float* tB   = sym_addr_f(g_tB);

    const float scale_q    = 0.08838834764831845f;  // 1/sqrt(128)
    const float inv_sqrt_m = 0.0625f;               // 1/sqrt(256)

    // 1. Xn = LN(X; ln1)
    ln_kernel<<<BS, 128>>>(X, nullptr, nullptr, ln1_g, ln1_b, Xn);

    // 2-4. q/k/v projections  [16384,128] @ [128,1024]
    gemm_kernel<0,false><<<dim3(HK/64, BS/64), 256>>>(Q,  Wq, q, bq, nullptr, scale_q, BS, HK, DD, 0);
    gemm_kernel<0,false><<<dim3(HK/64, BS/64), 256>>>(Xn, Wk, k, bk, nullptr, 1.0f,    BS, HK, DD, 0);
    gemm_kernel<0,false><<<dim3(HK/64, BS/64), 256>>>(Xn, Wv, v, bv, nullptr, 1.0f,    BS, HK, DD, 0);

    // 5-6. feature maps  [131072,128] @ proj^T[128,256], elu+1, scale, mask(kp)
    gemm_kernel<2,true><<<dim3(MM/64, BSH/64), 256>>>(q, proj, qp, nullptr, nullptr, inv_sqrt_m, BSH, MM, KK, HH);
    gemm_kernel<2,true><<<dim3(MM/64, BSH/64), 256>>>(k, proj, kp, nullptr, mask,    inv_sqrt_m, BSH, MM, KK, HH);

    // 7-9. kv, ksum, denom
    kv_kernel<<<dim3(KK/64, MM/64, BB*HH), 256>>>(kp, v, kv);
    ksum_kernel<<<BB*HH, MM>>>(kp, ks);
    denom_kernel<<<BSH/8, 256>>>(qp, ks, dn);

    // 10. attn = (qp @ kv) * denom
    attn_kernel<<<dim3(KK/64, SS/64, BB*HH), 256>>>(qp, kv, dn, attn);

    // 11. attn_out = attn[BS,1024] @ Wo[1024,128] + bo
    gemm_kernel<0,false><<<dim3(DD/64, BS/64), 256>>>(attn, Wo, ao, bo, nullptr, 1.0f, BS, DD, HK, 0);

    // 12. out1 = LN(Xn + ao*mask; ln2)
    ln_kernel<<<BS, 128>>>(Xn, ao, mask, ln2_g, ln2_b, out1);

    // 13-16. FFN: tA = LN(out1; fln0); tB = elu(tA@w0+b0); tA = LN(tB; fln1); out = tA@w1+b1
    ln_kernel<<<BS, 128>>>(out1, nullptr, nullptr, fln0_g, fln0_b, tA);
    gemm_kernel<1,false><<<dim3(DD/64, BS/64), 256>>>(tA, f_w0, tB, f_b0, nullptr, 1.0f, BS, DD, DD, 0);
    ln_kernel<<<BS, 128>>>(tB, nullptr, nullptr, fln1_g, fln1_b, tA);
    gemm_kernel<0,false><<<dim3(DD/64, BS/64), 256>>>(tA, f_w1, out, f_b1, nullptr, 1.0f, BS, DD, DD, 0);
}

// round 2
// speedup vs baseline: 1.5500x; 1.5500x over previous
#include <cuda_runtime.h>
#include <cuda_bf16.h>
#include <math.h>

// Problem constants
#define BB 4
#define SS 4096
#define DD 128
#define HH 8
#define KK 128
#define MM 256

#define BS   (BB*SS)        // 16384
#define BSH  (BB*SS*HH)     // 131072
#define HK   (HH*KK)        // 1024
#define HM   (HH*MM)        // 2048

// -------- scratch (static device globals; no allocation allowed) --------
__device__ float g_Xn  [BS*DD];
__device__ float g_q   [BS*HK];
__device__ float g_k   [BS*HK];
__device__ float g_v   [BS*HK];
__device__ float g_qp  [(size_t)BSH*MM];
__device__ float g_kp  [(size_t)BSH*MM];
__device__ float g_kv  [BB*HH*MM*KK];          // 1M floats
__device__ float g_part[8388608];              // split-K partials (kv: 8*32*32768, Wo: 4*2097152)
__device__ float g_ksp [32*16*256];            // ksum partials
__device__ float g_ks  [BB*HH*MM];
__device__ float g_dn  [BSH];
__device__ float g_attn[(size_t)BS*HK];
__device__ float g_ao  [BS*DD];
__device__ float g_out1[BS*DD];
__device__ float g_tA  [BS*DD];
__device__ float g_tB  [BS*DD];

// ---------------- LayerNorm (eps=1e-3), optional residual+mask ----------------
__global__ void ln_kernel(const float* __restrict__ in1, const float* __restrict__ in2,
                          const int* __restrict__ mask,
                          const float* __restrict__ gamma, const float* __restrict__ beta,
                          float* __restrict__ out)
{
    int row = blockIdx.x;
    int t = threadIdx.x;              // 128 threads, one per feature
    float x = in1[(size_t)row*DD + t];
    if (in2) {
        float mf = mask ? (float)mask[row] : 1.0f;
        x += in2[(size_t)row*DD + t] * mf;
    }
    __shared__ float sm[4];
    float s = x;
    #pragma unroll
    for (int o = 16; o; o >>= 1) s += __shfl_down_sync(0xffffffffu, s, o);
    if ((t & 31) == 0) sm[t >> 5] = s;
    __syncthreads();
    float mu = (sm[0] + sm[1] + sm[2] + sm[3]) * (1.0f/128.0f);
    float d = x - mu;
    float s2 = d * d;
    __syncthreads();
    #pragma unroll
    for (int o = 16; o; o >>= 1) s2 += __shfl_down_sync(0xffffffffu, s2, o);
    if ((t & 31) == 0) sm[t >> 5] = s2;
    __syncthreads();
    float var = (sm[0] + sm[1] + sm[2] + sm[3]) * (1.0f/128.0f);
    out[(size_t)row*DD + t] = d * rsqrtf(var + 1e-3f) * gamma[t] + beta[t];
}

// ================= 128x128 double-buffered SGEMM =================
// Tile: 128x128, 256 threads, 8x8 per thread, KTILE=16.
// AMODE 0: A is [M, lda] row-major (contraction index contiguous)  -> transpose into As
// AMODE 1: A is [Kd, lda] (M index contiguous)                     -> direct copy
// BMODE 0: B is [Kd, ldb] (N index contiguous)                     -> direct copy
// BMODE 1: B is [N, ldb] (contraction index contiguous)            -> transpose into Bs
// EPI 0: C = (acc + bias[n]) * alpha
// EPI 1: C = elu(acc + bias[n])
// EPI 2: C = (elu(acc)+1) * alpha * maskf(row/Hrep)
// EPI 3: C = acc                     (split-K partial)
// EPI 4: C = acc * denom[(b*S+row)*8+h]
#define KTILE 16
#define SPAD 132

// mode==0: transpose path; mode==1: direct path
template<int MODE>
__device__ __forceinline__ void g_load(const float* __restrict__ P, int ld, int base,
                                       int kt, int tid, float4* r)
{
    if constexpr (MODE == 0) {
        #pragma unroll
        for (int i = 0; i < 2; i++) {
            int m = (tid >> 2) + i*64, c4 = tid & 3;
            r[i] = *reinterpret_cast<const float4*>(P + (size_t)(base + m)*ld + kt + c4*4);
        }
    } else {
        #pragma unroll
        for (int i = 0; i < 2; i++) {
            int kk = (tid >> 5) + i*8, m4 = tid & 31;
            r[i] = *reinterpret_cast<const float4*>(P + (size_t)(kt + kk)*ld + base + m4*4);
        }
    }
}

template<int MODE>
__device__ __forceinline__ void s_store(float (*S)[SPAD], int tid, const float4* r)
{
    if constexpr (MODE == 0) {
        #pragma unroll
        for (int i = 0; i < 2; i++) {
            int m = (tid >> 2) + i*64, c4 = tid & 3;
            S[c4*4+0][m] = r[i].x; S[c4*4+1][m] = r[i].y;
            S[c4*4+2][m] = r[i].z; S[c4*4+3][m] = r[i].w;
        }
    } else {
        #pragma unroll
        for (int i = 0; i < 2; i++) {
            int kk = (tid >> 5) + i*8, m4 = tid & 31;
            *reinterpret_cast<float4*>(&S[kk][m4*4]) = r[i];
        }
    }
}

template<int AMODE, int BMODE, int EPI, int NSPLIT>
__global__ void __launch_bounds__(256) gemm128(
    const float* __restrict__ A, const float* __restrict__ B, float* __restrict__ C,
    const float* __restrict__ bias, const int* __restrict__ mask,
    const float* __restrict__ dn, float alpha,
    int M, int N, int Kd, int lda, int ldb, int ldc,
    long long sAb, long long sAh, long long sBb, long long sBh,
    long long sCb, long long sCh, long long sCs, int Hrep)
{
    int z = blockIdx.z;
    int split = z % NSPLIT, bh = z / NSPLIT;
    int b = bh >> 3, h = bh & 7;
    A += (long long)b*sAb + (long long)h*sAh;
    B += (long long)b*sBb + (long long)h*sBh;
    C += (long long)b*sCb + (long long)h*sCh + (long long)split*sCs;
    int kchunk = Kd / NSPLIT;
    int kbeg = split * kchunk;

    __shared__ float As[2][KTILE][SPAD];
    __shared__ float Bs[2][KTILE][SPAD];

    int tid = threadIdx.x;
    int tx = tid & 15, ty = tid >> 4;
    int m0 = blockIdx.y * 128, n0 = blockIdx.x * 128;

    float acc[8][8] = {};
    float4 ra[2], rb[2];

    constexpr int BLM = (BMODE == 0) ? 1 : 0;   // B direct iff BMODE==0

    g_load<AMODE>(A, lda, m0, kbeg, tid, ra);
    g_load<BLM>  (B, ldb, n0, kbeg, tid, rb);
    s_store<AMODE>(As[0], tid, ra);
    s_store<BLM>  (Bs[0], tid, rb);
    __syncthreads();

    int nk = kchunk / KTILE;
    for (int it = 0; it < nk; it++) {
        int buf = it & 1;
        if (it + 1 < nk) {
            g_load<AMODE>(A, lda, m0, kbeg + (it+1)*KTILE, tid, ra);
            g_load<BLM>  (B, ldb, n0, kbeg + (it+1)*KTILE, tid, rb);
        }
        #pragma unroll
        for (int kk = 0; kk < KTILE; kk++) {
            float a[8], bb[8];
            *reinterpret_cast<float4*>(&a[0]) = *reinterpret_cast<const float4*>(&As[buf][kk][ty*4]);
            *reinterpret_cast<float4*>(&a[4]) = *reinterpret_cast<const float4*>(&As[buf][kk][ty*4+64]);
            *reinterpret_cast<float4*>(&bb[0]) = *reinterpret_cast<const float4*>(&Bs[buf][kk][tx*4]);
            *reinterpret_cast<float4*>(&bb[4]) = *reinterpret_cast<const float4*>(&Bs[buf][kk][tx*4+64]);
            #pragma unroll
            for (int i = 0; i < 8; i++)
                #pragma unroll
                for (int j = 0; j < 8; j++)
                    acc[i][j] = fmaf(a[i], bb[j], acc[i][j]);
        }
        if (it + 1 < nk) {
            s_store<AMODE>(As[buf ^ 1], tid, ra);
            s_store<BLM>  (Bs[buf ^ 1], tid, rb);
            __syncthreads();
        }
    }

    // epilogue
    #pragma unroll
    for (int gi = 0; gi < 2; gi++) {
        #pragma unroll
        for (int r = 0; r < 4; r++) {
            int mrow = m0 + ty*4 + gi*64 + r;
            int ai = gi*4 + r;
            float mf = 1.0f, dnv = 1.0f;
            if (EPI == 2) mf = mask ? (float)mask[mrow / Hrep] : 1.0f;
            if (EPI == 4) dnv = dn[((size_t)(b*SS + mrow))*8 + h];
            #pragma unroll
            for (int gj = 0; gj < 2; gj++) {
                float4 o;
                #pragma unroll
                for (int c = 0; c < 4; c++) {
                    int ncol = n0 + tx*4 + gj*64 + c;
                    float v = acc[ai][gj*4 + c];
                    if (EPI == 0)      { if (bias) v += bias[ncol]; v *= alpha; }
                    else if (EPI == 1) { v += bias[ncol]; v = v > 0.0f ? v : expm1f(v); }
                    else if (EPI == 2) { v = v > 0.0f ? v + 1.0f : expf(v); v *= alpha * mf; }
                    else if (EPI == 4) { v *= dnv; }
                    (&o.x)[c] = v;
                }
                *reinterpret_cast<float4*>(C + (size_t)mrow*ldc + n0 + tx*4 + gj*64) = o;
            }
        }
    }
}

// ---------------- split-K reduces ----------------
__global__ void reduce_kv_kernel(const float* __restrict__ part, float* __restrict__ kv)
{
    size_t i = (size_t)blockIdx.x*256 + threadIdx.x;   // 32 * 32768 total
    size_t bh = i >> 15, off = i & 32767;
    float s = 0.0f;
    #pragma unroll
    for (int sp = 0; sp < 8; sp++) s += part[(bh*8 + sp)*32768 + off];
    kv[i] = s;
}

__global__ void reduce_wo_kernel(const float* __restrict__ part, const float* __restrict__ bias,
                                 float* __restrict__ out)
{
    size_t i = (size_t)blockIdx.x*256 + threadIdx.x;   // 16384*128 total
    float s = bias[i & 127];
    #pragma unroll
    for (int sp = 0; sp < 4; sp++) s += part[(size_t)sp*2097152 + i];
    out[i] = s;
}

// ---------------- ksum: partials over s-chunks, then reduce ----------------
__global__ void ksum_part_kernel(const float* __restrict__ kp, float* __restrict__ part)
{
    int bh = blockIdx.x, ch = blockIdx.y, m = threadIdx.x;
    int b = bh >> 3, h = bh & 7;
    const float* p = kp + (size_t)b*SS*HM + (size_t)h*MM + (size_t)(ch*256)*HM + m;
    float s = 0.0f;
    for (int i = 0; i < 256; i++) s += p[(size_t)i*HM];
    part[((size_t)bh*16 + ch)*256 + m] = s;
}

__global__ void ksum_reduce_kernel(const float* __restrict__ part, float* __restrict__ ks)
{
    int bh = blockIdx.x, m = threadIdx.x;
    float s = 0.0f;
    #pragma unroll
    for (int c = 0; c < 16; c++) s += part[((size_t)bh*16 + c)*256 + m];
    ks[bh*256 + m] = s;
}

// ---------------- denom[r] = 1/(qp[r,:]·ksum[b,h,:] + 1e-6) ----------------
__global__ void denom_kernel(const float* __restrict__ qp, const float* __restrict__ ksum,
                             float* __restrict__ denom)
{
    int warp = threadIdx.x >> 5, lane = threadIdx.x & 31;
    int r = blockIdx.x * 8 + warp;
    const float* q = qp + (size_t)r * MM;
    int b = r / (SS * HH);
    int h = r & 7;
    const float* ks = ksum + (b*HH + h) * MM;
    float s = 0.0f;
    for (int i = lane; i < MM; i += 32) s += q[i] * ks[i];
    #pragma unroll
    for (int o = 16; o; o >>= 1) s += __shfl_down_sync(0xffffffffu, s, o);
    if (lane == 0) denom[r] = 1.0f / (s + 1e-6f);
}

// ---------------- host-side launch ----------------
static float* sym_addr_f(const void* sym)
{
    void* p = nullptr;
    cudaGetSymbolAddress(&p, sym);
    return (float*)p;
}

extern "C" void kernel_launch(void* const* d_in, const int* in_sizes, int n_in,
                              void* d_out, int out_size)
{
    (void)in_sizes; (void)n_in; (void)out_size;
    const float* Q      = (const float*)d_in[0];
    const float* X      = (const float*)d_in[1];
    const int*   mask   = (const int*)  d_in[2];
    const float* Wq     = (const float*)d_in[3];
    const float* bq     = (const float*)d_in[4];
    const float* Wk     = (const float*)d_in[5];
    const float* bk     = (const float*)d_in[6];
    const float* Wv     = (const float*)d_in[7];
    const float* bv     = (const float*)d_in[8];
    const float* Wo     = (const float*)d_in[9];
    const float* bo     = (const float*)d_in[10];
    const float* proj   = (const float*)d_in[11];
    const float* ln1_g  = (const float*)d_in[12];
    const float* ln1_b  = (const float*)d_in[13];
    const float* ln2_g  = (const float*)d_in[14];
    const float* ln2_b  = (const float*)d_in[15];
    const float* fln0_g = (const float*)d_in[16];
    const float* fln0_b = (const float*)d_in[17];
    const float* f_w0   = (const float*)d_in[18];
    const float* f_b0   = (const float*)d_in[19];
    const float* fln1_g = (const float*)d_in[20];
    const float* fln1_b = (const float*)d_in[21];
    const float* f_w1   = (const float*)d_in[22];
    const float* f_b1   = (const float*)d_in[23];
    float* out = (float*)d_out;

    float* Xn   = sym_addr_f(g_Xn);
    float* q    = sym_addr_f(g_q);
    float* k    = sym_addr_f(g_k);
    float* v    = sym_addr_f(g_v);
    float* qp   = sym_addr_f(g_qp);
    float* kp   = sym_addr_f(g_kp);
    float* kv   = sym_addr_f(g_kv);
    float* part = sym_addr_f(g_part);
    float* ksp  = sym_addr_f(g_ksp);
    float* ks   = sym_addr_f(g_ks);
    float* dn   = sym_addr_f(g_dn);
    float* attn = sym_addr_f(g_attn);
    float* ao   = sym_addr_f(g_ao);
    float* out1 = sym_addr_f(g_out1);
    float* tA   = sym_addr_f(g_tA);
    float* tB   = sym_addr_f(g_tB);

    const float scale_q    = 0.08838834764831845f;  // 1/sqrt(128)
    const float inv_sqrt_m = 0.0625f;               // 1/sqrt(256)

    // 1. Xn = LN(X; ln1)
    ln_kernel<<<BS, 128>>>(X, nullptr, nullptr, ln1_g, ln1_b, Xn);

    // 2-4. q/k/v projections  [16384,128] @ [128,1024]
    gemm128<0,0,0,1><<<dim3(HK/128, BS/128, 1), 256>>>(Q,  Wq, q, bq, nullptr, nullptr, scale_q,
        BS, HK, DD, DD, HK, HK, 0,0,0,0, 0,0,0, 0);
    gemm128<0,0,0,1><<<dim3(HK/128, BS/128, 1), 256>>>(Xn, Wk, k, bk, nullptr, nullptr, 1.0f,
        BS, HK, DD, DD, HK, HK, 0,0,0,0, 0,0,0, 0);
    gemm128<0,0,0,1><<<dim3(HK/128, BS/128, 1), 256>>>(Xn, Wv, v, bv, nullptr, nullptr, 1.0f,
        BS, HK, DD, DD, HK, HK, 0,0,0,0, 0,0,0, 0);

    // 5-6. feature maps  [131072,128] @ proj^T[128,256], (elu+1)*inv_sqrt_m, mask(kp only)
    gemm128<0,1,2,1><<<dim3(MM/128, BSH/128, 1), 256>>>(q, proj, qp, nullptr, nullptr, nullptr, inv_sqrt_m,
        BSH, MM, KK, KK, KK, MM, 0,0,0,0, 0,0,0, HH);
    gemm128<0,1,2,1><<<dim3(MM/128, BSH/128, 1), 256>>>(k, proj, kp, nullptr, mask, nullptr, inv_sqrt_m,
        BSH, MM, KK, KK, KK, MM, 0,0,0,0, 0,0,0, HH);

    // 7. kv[bh] = kp^T @ v, split-K=8 partials -> reduce
    gemm128<1,0,3,8><<<dim3(KK/128, MM/128, 32*8), 256>>>(kp, v, part, nullptr, nullptr, nullptr, 1.0f,
        MM, KK, SS, HM, HK, KK,
        (long long)SS*HM, MM, (long long)SS*HK, KK,
        64LL*32768, 8LL*32768, 32768LL, 0);
    reduce_kv_kernel<<<(32*32768)/256, 256>>>(part, kv);

    // 8. ksum
    ksum_part_kernel<<<dim3(32, 16), 256>>>(kp, ksp);
    ksum_reduce_kernel<<<32, 256>>>(ksp, ks);

    // 9. denom
    denom_kernel<<<BSH/8, 256>>>(qp, ks, dn);

    // 10. attn[bh] = (qp @ kv) * denom
    gemm128<0,0,4,1><<<dim3(KK/128, SS/128, 32), 256>>>(qp, kv, attn, nullptr, nullptr, dn, 1.0f,
        SS, KK, MM, HM, KK, HK,
        (long long)SS*HM, MM, 8LL*MM*KK, (long long)MM*KK,
        (long long)SS*HK, KK, 0, 0);

    // 11. attn_out = attn[16384,1024] @ Wo[1024,128], split-K=4 -> reduce(+bo)
    gemm128<0,0,3,4><<<dim3(DD/128, BS/128, 4), 256>>>(attn, Wo, part, nullptr, nullptr, nullptr, 1.0f,
        BS, DD, HK, HK, DD, DD,
        0,0,0,0, 0,0, 2097152LL, 0);
    reduce_wo_kernel<<<(BS*DD)/256, 256>>>(part, bo, ao);

    // 12. out1 = LN(Xn + ao*mask; ln2)
    ln_kernel<<<BS, 128>>>(Xn, ao, mask, ln2_g, ln2_b, out1);

    // 13-16. FFN
    ln_kernel<<<BS, 128>>>(out1, nullptr, nullptr, fln0_g, fln0_b, tA);
    gemm128<0,0,1,1><<<dim3(DD/128, BS/128, 1), 256>>>(tA, f_w0, tB, f_b0, nullptr, nullptr, 1.0f,
        BS, DD, DD, DD, DD, DD, 0,0,0,0, 0,0,0, 0);
    ln_kernel<<<BS, 128>>>(tB, nullptr, nullptr, fln1_g, fln1_b, tA);
    gemm128<0,0,0,1><<<dim3(DD/128, BS/128, 1), 256>>>(tA, f_w1, out, f_b1, nullptr, nullptr, 1.0f,
        BS, DD, DD, DD, DD, DD, 0,0,0,0, 0,0,0, 0);
}

// round 4
// speedup vs baseline: 1.7381x; 1.1213x over previous
#include <cuda_runtime.h>
#include <cuda_bf16.h>
#include <math.h>
#include <stdint.h>

// Problem constants
#define BB 4
#define SS 4096
#define DD 128
#define HH 8
#define KK 128
#define MM 256

#define BS   (BB*SS)        // 16384
#define BSH  (BB*SS*HH)     // 131072
#define HK   (HH*KK)        // 1024
#define HM   (HH*MM)        // 2048

// -------- scratch (static device globals; no allocation allowed) --------
__device__ float g_Xn  [BS*DD];
__device__ float g_q   [BS*HK];
__device__ float g_k   [BS*HK];
__device__ float g_v   [BS*HK];
__device__ float g_qp  [(size_t)BSH*MM];
__device__ float g_kp  [(size_t)BSH*MM];
__device__ float g_kv  [BB*HH*MM*KK];          // 1M floats
__device__ float g_part[8388608];              // split-K partials
__device__ float g_ksp [32*16*256];            // ksum partials
__device__ float g_ks  [BB*HH*MM];
__device__ float g_dn  [BSH];
__device__ float g_attn[(size_t)BS*HK];
__device__ float g_ao  [BS*DD];
__device__ float g_out1[BS*DD];
__device__ float g_tA  [BS*DD];
__device__ float g_tB  [BS*DD];

// ================= warp-MMA helpers (sm_100-base-ISA safe) =================
__device__ __forceinline__ uint32_t smem_u32(const void* p) {
    uint32_t a;
    asm("{ .reg .u64 t; cvta.to.shared.u64 t, %1; cvt.u32.u64 %0, t; }" : "=r"(a) : "l"(p));
    return a;
}
__device__ __forceinline__ void ldsm4(uint32_t* r, uint32_t a) {
    asm volatile("ldmatrix.sync.aligned.m8n8.x4.shared.b16 {%0,%1,%2,%3}, [%4];"
        : "=r"(r[0]), "=r"(r[1]), "=r"(r[2]), "=r"(r[3]) : "r"(a));
}
__device__ __forceinline__ void ldsm2(uint32_t* r, uint32_t a) {
    asm volatile("ldmatrix.sync.aligned.m8n8.x2.shared.b16 {%0,%1}, [%2];"
        : "=r"(r[0]), "=r"(r[1]) : "r"(a));
}
__device__ __forceinline__ void mma_bf16(float* d, const uint32_t* a, const uint32_t* b) {
    asm volatile("mma.sync.aligned.m16n8k16.row.col.f32.bf16.bf16.f32 "
        "{%0,%1,%2,%3}, {%4,%5,%6,%7}, {%8,%9}, {%0,%1,%2,%3};"
        : "+f"(d[0]), "+f"(d[1]), "+f"(d[2]), "+f"(d[3])
        : "r"(a[0]), "r"(a[1]), "r"(a[2]), "r"(a[3]), "r"(b[0]), "r"(b[1]));
}

// ---------------- tile loaders: fp32 global -> bf16 hi/lo SW128 SMEM ----------------
// Tile is [128 rows, 64 k] bf16, 128 bytes/row, SW128-swizzled. 256 threads.
// TR=false: element (r, kc) = G[(base0+r)*ld + k0 + kc]
// TR=true : element (r, kc) = G[(k0+kc)*ld + base0 + r]
template<bool TR>
__device__ __forceinline__ void load_tile(char* shi, char* slo,
    const float* __restrict__ G, int ld, int base0, int k0, int tid)
{
    if constexpr (!TR) {
        #pragma unroll
        for (int i = 0; i < 8; i++) {
            int idx = tid + i*256;
            int r = idx >> 4, c4 = idx & 15;
            float4 v = *reinterpret_cast<const float4*>(G + (size_t)(base0 + r)*ld + k0 + c4*4);
            __nv_bfloat16 h0 = __float2bfloat16(v.x);
            __nv_bfloat16 h1 = __float2bfloat16(v.y);
            __nv_bfloat16 h2 = __float2bfloat16(v.z);
            __nv_bfloat16 h3 = __float2bfloat16(v.w);
            __nv_bfloat16 l0 = __float2bfloat16(v.x - __bfloat162float(h0));
            __nv_bfloat16 l1 = __float2bfloat16(v.y - __bfloat162float(h1));
            __nv_bfloat16 l2 = __float2bfloat16(v.z - __bfloat162float(h2));
            __nv_bfloat16 l3 = __float2bfloat16(v.w - __bfloat162float(h3));
            int off = r*128 + c4*8;
            int sw = off ^ ((off >> 3) & 0x70);
            *reinterpret_cast<__nv_bfloat162*>(shi + sw)     = __nv_bfloat162(h0, h1);
            *reinterpret_cast<__nv_bfloat162*>(shi + sw + 4) = __nv_bfloat162(h2, h3);
            *reinterpret_cast<__nv_bfloat162*>(slo + sw)     = __nv_bfloat162(l0, l1);
            *reinterpret_cast<__nv_bfloat162*>(slo + sw + 4) = __nv_bfloat162(l2, l3);
        }
    } else {
        #pragma unroll
        for (int i = 0; i < 8; i++) {
            int idx = tid + i*256;
            int kk = idx >> 5, r4 = idx & 31;
            float4 v = *reinterpret_cast<const float4*>(G + (size_t)(k0 + kk)*ld + base0 + r4*4);
            #pragma unroll
            for (int j = 0; j < 4; j++) {
                float f = (&v.x)[j];
                __nv_bfloat16 hb = __float2bfloat16(f);
                __nv_bfloat16 lb = __float2bfloat16(f - __bfloat162float(hb));
                int off = (r4*4 + j)*128 + kk*2;
                int sw = off ^ ((off >> 3) & 0x70);
                *reinterpret_cast<__nv_bfloat16*>(shi + sw) = hb;
                *reinterpret_cast<__nv_bfloat16*>(slo + sw) = lb;
            }
        }
    }
}

// ================= bf16-split warp-MMA GEMM =================
// C[M,128] tile per CTA, K-tiles of 64. 256 threads, 8 warps in 2(m)x4(n),
// warp tile 64m x 32n, mma.sync m16n8k16.
// EPI 0: (acc + bias[n]) * alpha
// EPI 1: elu(acc + bias[n])
// EPI 2: (elu(acc)+1) * alpha * maskf(row>>3)
// EPI 3: acc (split-K partial)
// EPI 4: acc * dn[(b*S+row)*8+h]
template<bool ATR, bool BTR, int EPI, int NSPLIT>
__global__ void __launch_bounds__(256) tgemm(
    const float* __restrict__ A, const float* __restrict__ B, float* __restrict__ C,
    const float* __restrict__ bias, const int* __restrict__ mask,
    const float* __restrict__ dn, float alpha,
    int Kd, int lda, int ldb, int ldc,
    long long sAb, long long sAh, long long sBb, long long sBh,
    long long sCb, long long sCh, long long sCs)
{
    extern __shared__ char dyn[];
    const int ASZ = 128*128;          // bytes per half tile (128 rows x 64 bf16)
    const int BUFSZ = 4*ASZ;          // Ahi, Alo, Bhi, Blo

    uint32_t dynU = smem_u32(dyn);
    uint32_t smU = (dynU + 1023u) & ~1023u;
    char* sm = dyn + (smU - dynU);

    int tid = threadIdx.x;
    int lane = tid & 31, wid = tid >> 5;
    int wm = (wid & 1) * 64, wn = (wid >> 1) * 32;

    int z = blockIdx.z;
    int split = z % NSPLIT, bh = z / NSPLIT;
    int b = bh >> 3, h = bh & 7;
    A += (long long)b*sAb + (long long)h*sAh;
    B += (long long)b*sBb + (long long)h*sBh;
    C += (long long)b*sCb + (long long)h*sCh + (long long)split*sCs;
    int kchunk = Kd / NSPLIT;
    int kbeg = split * kchunk;
    int nk = kchunk / 64;
    int m0 = blockIdx.y * 128, n0 = blockIdx.x * 128;

    float acc[4][4][4] = {};

    // preload tile 0
    load_tile<ATR>(sm,         sm + ASZ,   A, lda, m0, kbeg, tid);
    load_tile<BTR>(sm + 2*ASZ, sm + 3*ASZ, B, ldb, n0, kbeg, tid);
    __syncthreads();

    // per-lane ldmatrix row offsets (rows fixed across ksteps)
    int rA = wm + (lane & 15);          // + mi*16
    int rB = wn + (lane & 7);           // + ni*8
    int cAbase = lane >> 4;             // 0/1 chunk offset
    int cBbase = (lane >> 3) & 1;

    for (int it = 0; it < nk; it++) {
        int buf = it & 1;
        if (it + 1 < nk) {
            char* d0 = sm + (buf ^ 1)*BUFSZ;
            load_tile<ATR>(d0,         d0 + ASZ,   A, lda, m0, kbeg + (it+1)*64, tid);
            load_tile<BTR>(d0 + 2*ASZ, d0 + 3*ASZ, B, ldb, n0, kbeg + (it+1)*64, tid);
        }
        uint32_t aH = smU + buf*BUFSZ;
        uint32_t aL = aH + ASZ;
        uint32_t bH = aH + 2*ASZ;
        uint32_t bL = aH + 3*ASZ;
        #pragma unroll
        for (int ks = 0; ks < 4; ks++) {
            uint32_t afh[4][4], afl[4][4], bfh[4][2], bfl[4][2];
            #pragma unroll
            for (int mi = 0; mi < 4; mi++) {
                int row = rA + mi*16;
                int sw = row*128 + (((ks*2 + cAbase) ^ (row & 7)) * 16);
                ldsm4(afh[mi], aH + sw);
                ldsm4(afl[mi], aL + sw);
            }
            #pragma unroll
            for (int ni = 0; ni < 4; ni++) {
                int row = rB + ni*8;
                int sw = row*128 + (((ks*2 + cBbase) ^ (row & 7)) * 16);
                ldsm2(bfh[ni], bH + sw);
                ldsm2(bfl[ni], bL + sw);
            }
            #pragma unroll
            for (int mi = 0; mi < 4; mi++)
                #pragma unroll
                for (int ni = 0; ni < 4; ni++) {
                    mma_bf16(acc[mi][ni], afh[mi], bfh[ni]);
                    mma_bf16(acc[mi][ni], afh[mi], bfl[ni]);
                    mma_bf16(acc[mi][ni], afl[mi], bfh[ni]);
                }
        }
        __syncthreads();
    }

    // ---------------- epilogue ----------------
    #pragma unroll
    for (int mi = 0; mi < 4; mi++) {
        int r0 = m0 + wm + mi*16 + (lane >> 2);
        int r1 = r0 + 8;
        float f0 = 1.0f, f1 = 1.0f;               // row factors
        if (EPI == 2) {
            f0 = mask ? (float)mask[r0 >> 3] : 1.0f;
            f1 = mask ? (float)mask[r1 >> 3] : 1.0f;
        } else if (EPI == 4) {
            f0 = dn[((size_t)(b*SS + r0))*8 + h];
            f1 = dn[((size_t)(b*SS + r1))*8 + h];
        }
        #pragma unroll
        for (int ni = 0; ni < 4; ni++) {
            int c0 = n0 + wn + ni*8 + (lane & 3)*2;
            float d0 = acc[mi][ni][0], d1 = acc[mi][ni][1];
            float d2 = acc[mi][ni][2], d3 = acc[mi][ni][3];
            if (EPI == 0) {
                float b0 = bias ? bias[c0] : 0.0f, b1 = bias ? bias[c0+1] : 0.0f;
                d0 = (d0 + b0)*alpha; d1 = (d1 + b1)*alpha;
                d2 = (d2 + b0)*alpha; d3 = (d3 + b1)*alpha;
            } else if (EPI == 1) {
                float b0 = bias[c0], b1 = bias[c0+1];
                d0 += b0; d1 += b1; d2 += b0; d3 += b1;
                d0 = d0 > 0.0f ? d0 : expm1f(d0);
                d1 = d1 > 0.0f ? d1 : expm1f(d1);
                d2 = d2 > 0.0f ? d2 : expm1f(d2);
                d3 = d3 > 0.0f ? d3 : expm1f(d3);
            } else if (EPI == 2) {
                d0 = (d0 > 0.0f ? d0 + 1.0f : expf(d0)) * alpha * f0;
                d1 = (d1 > 0.0f ? d1 + 1.0f : expf(d1)) * alpha * f0;
                d2 = (d2 > 0.0f ? d2 + 1.0f : expf(d2)) * alpha * f1;
                d3 = (d3 > 0.0f ? d3 + 1.0f : expf(d3)) * alpha * f1;
            } else if (EPI == 4) {
                d0 *= f0; d1 *= f0; d2 *= f1; d3 *= f1;
            }
            *reinterpret_cast<float2*>(C + (size_t)r0*ldc + c0) = make_float2(d0, d1);
            *reinterpret_cast<float2*>(C + (size_t)r1*ldc + c0) = make_float2(d2, d3);
        }
    }
}

// ---------------- LayerNorm (eps=1e-3), optional residual+mask ----------------
__global__ void ln_kernel(const float* __restrict__ in1, const float* __restrict__ in2,
                          const int* __restrict__ mask,
                          const float* __restrict__ gamma, const float* __restrict__ beta,
                          float* __restrict__ out)
{
    int row = blockIdx.x;
    int t = threadIdx.x;
    float x = in1[(size_t)row*DD + t];
    if (in2) {
        float mf = mask ? (float)mask[row] : 1.0f;
        x += in2[(size_t)row*DD + t] * mf;
    }
    __shared__ float smv[4];
    float s = x;
    #pragma unroll
    for (int o = 16; o; o >>= 1) s += __shfl_down_sync(0xffffffffu, s, o);
    if ((t & 31) == 0) smv[t >> 5] = s;
    __syncthreads();
    float mu = (smv[0] + smv[1] + smv[2] + smv[3]) * (1.0f/128.0f);
    float d = x - mu;
    float s2 = d * d;
    __syncthreads();
    #pragma unroll
    for (int o = 16; o; o >>= 1) s2 += __shfl_down_sync(0xffffffffu, s2, o);
    if ((t & 31) == 0) smv[t >> 5] = s2;
    __syncthreads();
    float var = (smv[0] + smv[1] + smv[2] + smv[3]) * (1.0f/128.0f);
    out[(size_t)row*DD + t] = d * rsqrtf(var + 1e-3f) * gamma[t] + beta[t];
}

// ---------------- split-K reduces ----------------
__global__ void reduce_kv_kernel(const float* __restrict__ part, float* __restrict__ kv)
{
    size_t i = (size_t)blockIdx.x*256 + threadIdx.x;   // 32 * 32768 total
    size_t bh = i >> 15, off = i & 32767;
    float s = 0.0f;
    #pragma unroll
    for (int sp = 0; sp < 8; sp++) s += part[(bh*8 + sp)*32768 + off];
    kv[i] = s;
}

__global__ void reduce_wo_kernel(const float* __restrict__ part, const float* __restrict__ bias,
                                 float* __restrict__ out)
{
    size_t i = (size_t)blockIdx.x*256 + threadIdx.x;   // 16384*128 total
    float s = bias[i & 127];
    #pragma unroll
    for (int sp = 0; sp < 4; sp++) s += part[(size_t)sp*2097152 + i];
    out[i] = s;
}

// ---------------- ksum ----------------
__global__ void ksum_part_kernel(const float* __restrict__ kp, float* __restrict__ part)
{
    int bh = blockIdx.x, ch = blockIdx.y, m = threadIdx.x;
    int b = bh >> 3, h = bh & 7;
    const float* p = kp + (size_t)b*SS*HM + (size_t)h*MM + (size_t)(ch*256)*HM + m;
    float s = 0.0f;
    for (int i = 0; i < 256; i++) s += p[(size_t)i*HM];
    part[((size_t)bh*16 + ch)*256 + m] = s;
}

__global__ void ksum_reduce_kernel(const float* __restrict__ part, float* __restrict__ ks)
{
    int bh = blockIdx.x, m = threadIdx.x;
    float s = 0.0f;
    #pragma unroll
    for (int c = 0; c < 16; c++) s += part[((size_t)bh*16 + c)*256 + m];
    ks[bh*256 + m] = s;
}

// ---------------- denom ----------------
__global__ void denom_kernel(const float* __restrict__ qp, const float* __restrict__ ksum,
                             float* __restrict__ denom)
{
    int warp = threadIdx.x >> 5, lane = threadIdx.x & 31;
    int r = blockIdx.x * 8 + warp;
    const float* q = qp + (size_t)r * MM;
    int b = r / (SS * HH);
    int h = r & 7;
    const float* ks = ksum + (b*HH + h) * MM;
    float s = 0.0f;
    for (int i = lane; i < MM; i += 32) s += q[i] * ks[i];
    #pragma unroll
    for (int o = 16; o; o >>= 1) s += __shfl_down_sync(0xffffffffu, s, o);
    if (lane == 0) denom[r] = 1.0f / (s + 1e-6f);
}

// ---------------- host-side launch ----------------
static float* sym_addr_f(const void* sym)
{
    void* p = nullptr;
    cudaGetSymbolAddress(&p, sym);
    return (float*)p;
}

#define SMEM_REQ (2*4*128*128 + 1024)   // 132096

extern "C" void kernel_launch(void* const* d_in, const int* in_sizes, int n_in,
                              void* d_out, int out_size)
{
    (void)in_sizes; (void)n_in; (void)out_size;
    const float* Q      = (const float*)d_in[0];
    const float* X      = (const float*)d_in[1];
    const int*   mask   = (const int*)  d_in[2];
    const float* Wq     = (const float*)d_in[3];
    const float* bq     = (const float*)d_in[4];
    const float* Wk     = (const float*)d_in[5];
    const float* bk     = (const float*)d_in[6];
    const float* Wv     = (const float*)d_in[7];
    const float* bv     = (const float*)d_in[8];
    const float* Wo     = (const float*)d_in[9];
    const float* bo     = (const float*)d_in[10];
    const float* proj   = (const float*)d_in[11];
    const float* ln1_g  = (const float*)d_in[12];
    const float* ln1_b  = (const float*)d_in[13];
    const float* ln2_g  = (const float*)d_in[14];
    const float* ln2_b  = (const float*)d_in[15];
    const float* fln0_g = (const float*)d_in[16];
    const float* fln0_b = (const float*)d_in[17];
    const float* f_w0   = (const float*)d_in[18];
    const float* f_b0   = (const float*)d_in[19];
    const float* fln1_g = (const float*)d_in[20];
    const float* fln1_b = (const float*)d_in[21];
    const float* f_w1   = (const float*)d_in[22];
    const float* f_b1   = (const float*)d_in[23];
    float* out = (float*)d_out;

    float* Xn   = sym_addr_f(g_Xn);
    float* q    = sym_addr_f(g_q);
    float* k    = sym_addr_f(g_k);
    float* v    = sym_addr_f(g_v);
    float* qp   = sym_addr_f(g_qp);
    float* kp   = sym_addr_f(g_kp);
    float* kv   = sym_addr_f(g_kv);
    float* part = sym_addr_f(g_part);
    float* ksp  = sym_addr_f(g_ksp);
    float* ks   = sym_addr_f(g_ks);
    float* dn   = sym_addr_f(g_dn);
    float* attn = sym_addr_f(g_attn);
    float* ao   = sym_addr_f(g_ao);
    float* out1 = sym_addr_f(g_out1);
    float* tA   = sym_addr_f(g_tA);
    float* tB   = sym_addr_f(g_tB);

    const float scale_q    = 0.08838834764831845f;  // 1/sqrt(128)
    const float inv_sqrt_m = 0.0625f;               // 1/sqrt(256)

    cudaFuncSetAttribute(tgemm<false,true ,0,1>, cudaFuncAttributeMaxDynamicSharedMemorySize, SMEM_REQ);
    cudaFuncSetAttribute(tgemm<false,false,2,1>, cudaFuncAttributeMaxDynamicSharedMemorySize, SMEM_REQ);
    cudaFuncSetAttribute(tgemm<true ,true ,3,8>, cudaFuncAttributeMaxDynamicSharedMemorySize, SMEM_REQ);
    cudaFuncSetAttribute(tgemm<false,true ,4,1>, cudaFuncAttributeMaxDynamicSharedMemorySize, SMEM_REQ);
    cudaFuncSetAttribute(tgemm<false,true ,3,4>, cudaFuncAttributeMaxDynamicSharedMemorySize, SMEM_REQ);
    cudaFuncSetAttribute(tgemm<false,true ,1,1>, cudaFuncAttributeMaxDynamicSharedMemorySize, SMEM_REQ);

    // 1. Xn = LN(X; ln1)
    ln_kernel<<<BS, 128>>>(X, nullptr, nullptr, ln1_g, ln1_b, Xn);

    // 2-4. q/k/v projections: [16384,128] @ Wq (Wq is [128,1024] -> B trans)
    tgemm<false,true,0,1><<<dim3(HK/128, BS/128, 1), 256, SMEM_REQ>>>(
        Q,  Wq, q, bq, nullptr, nullptr, scale_q, DD, DD, HK, HK, 0,0,0,0, 0,0,0);
    tgemm<false,true,0,1><<<dim3(HK/128, BS/128, 1), 256, SMEM_REQ>>>(
        Xn, Wk, k, bk, nullptr, nullptr, 1.0f,    DD, DD, HK, HK, 0,0,0,0, 0,0,0);
    tgemm<false,true,0,1><<<dim3(HK/128, BS/128, 1), 256, SMEM_REQ>>>(
        Xn, Wv, v, bv, nullptr, nullptr, 1.0f,    DD, DD, HK, HK, 0,0,0,0, 0,0,0);

    // 5-6. feature maps: [131072,128] @ proj[256,128] (B direct rows = n)
    tgemm<false,false,2,1><<<dim3(MM/128, BSH/128, 1), 256, SMEM_REQ>>>(
        q, proj, qp, nullptr, nullptr, nullptr, inv_sqrt_m, KK, KK, KK, MM, 0,0,0,0, 0,0,0);
    tgemm<false,false,2,1><<<dim3(MM/128, BSH/128, 1), 256, SMEM_REQ>>>(
        k, proj, kp, nullptr, mask,    nullptr, inv_sqrt_m, KK, KK, KK, MM, 0,0,0,0, 0,0,0);

    // 7. kv[bh][m][k] = sum_s kp[s,m] v[s,k]; A=kp^T (trans), B=v^T (trans); split-K=8
    tgemm<true,true,3,8><<<dim3(1, MM/128, 32*8), 256, SMEM_REQ>>>(
        kp, v, part, nullptr, nullptr, nullptr, 1.0f, SS, HM, HK, KK,
        (long long)SS*HM, MM, (long long)SS*HK, KK,
        2097152LL, 262144LL, 32768LL);
    reduce_kv_kernel<<<(32*32768)/256, 256>>>(part, kv);

    // 8. ksum
    ksum_part_kernel<<<dim3(32, 16), 256>>>(kp, ksp);
    ksum_reduce_kernel<<<32, 256>>>(ksp, ks);

    // 9. denom
    denom_kernel<<<BSH/8, 256>>>(qp, ks, dn);

    // 10. attn = (qp @ kv) * denom; A=qp direct (lda=HM), B=kv^T (trans, ldb=KK)
    tgemm<false,true,4,1><<<dim3(1, SS/128, 32), 256, SMEM_REQ>>>(
        qp, kv, attn, nullptr, nullptr, dn, 1.0f, MM, HM, KK, HK,
        (long long)SS*HM, MM, 262144LL, 32768LL,
        (long long)SS*HK, KK, 0);

    // 11. attn_out = attn[16384,1024] @ Wo ([1024,128] -> B trans), split-K=4
    tgemm<false,true,3,4><<<dim3(1, BS/128, 4), 256, SMEM_REQ>>>(
        attn, Wo, part, nullptr, nullptr, nullptr, 1.0f, HK, HK, DD, DD,
        0,0,0,0, 0,0, 2097152LL);
    reduce_wo_kernel<<<(BS*DD)/256, 256>>>(part, bo, ao);

    // 12. out1 = LN(Xn + ao*mask; ln2)
    ln_kernel<<<BS, 128>>>(Xn, ao, mask, ln2_g, ln2_b, out1);

    // 13-16. FFN
    ln_kernel<<<BS, 128>>>(out1, nullptr, nullptr, fln0_g, fln0_b, tA);
    tgemm<false,true,1,1><<<dim3(1, BS/128, 1), 256, SMEM_REQ>>>(
        tA, f_w0, tB, f_b0, nullptr, nullptr, 1.0f, DD, DD, DD, DD, 0,0,0,0, 0,0,0);
    ln_kernel<<<BS, 128>>>(tB, nullptr, nullptr, fln1_g, fln1_b, tA);
    tgemm<false,true,0,1><<<dim3(1, BS/128, 1), 256, SMEM_REQ>>>(
        tA, f_w1, out, f_b1, nullptr, nullptr, 1.0f, DD, DD, DD, DD, 0,0,0,0, 0,0,0);
}

// round 5
// speedup vs baseline: 2.1566x; 1.2407x over previous
#include <cuda_runtime.h>
#include <cuda_bf16.h>
#include <math.h>
#include <stdint.h>

// Problem constants
#define BB 4
#define SS 4096
#define DD 128
#define HH 8
#define KK 128
#define MM 256

#define BS   (BB*SS)        // 16384
#define BSH  (BB*SS*HH)     // 131072
#define HK   (HH*KK)        // 1024
#define HM   (HH*MM)        // 2048

typedef __nv_bfloat16 bf16;

// -------- scratch (static device globals) --------
__device__ float g_Xn  [BS*DD];
__device__ float g_part[8388608];
__device__ float g_ksp [32*16*256];
__device__ float g_ks  [BB*HH*MM];
__device__ float g_dn  [BSH];
__device__ float g_ao  [BS*DD];
__device__ float g_out1[BS*DD];
__device__ float g_tB  [BS*DD];

// bf16 hi/lo pairs: [0]=hi, [1]=lo
__device__ bf16 b_Q   [2][BS*DD];
__device__ bf16 b_Xn  [2][BS*DD];
__device__ bf16 b_WqT [2][HK*DD];
__device__ bf16 b_WkT [2][HK*DD];
__device__ bf16 b_WvT [2][HK*DD];
__device__ bf16 b_WoT [2][DD*HK];
__device__ bf16 b_proj[2][MM*KK];
__device__ bf16 b_fw0T[2][DD*DD];
__device__ bf16 b_fw1T[2][DD*DD];
__device__ bf16 b_q   [2][BS*HK];
__device__ bf16 b_k   [2][BS*HK];
__device__ bf16 b_v   [2][BS*HK];
__device__ bf16 b_qp  [2][(size_t)BSH*MM];
__device__ bf16 b_kp  [2][(size_t)BSH*MM];
__device__ bf16 b_kv  [2][BB*HH*MM*KK];
__device__ bf16 b_attn[2][(size_t)BS*HK];
__device__ bf16 b_tA  [2][BS*DD];

// ================= asm helpers =================
__device__ __forceinline__ uint32_t smem_u32(const void* p) {
    uint32_t a;
    asm("{ .reg .u64 t; cvta.to.shared.u64 t, %1; cvt.u32.u64 %0, t; }" : "=r"(a) : "l"(p));
    return a;
}
#define CP_ASYNC16(dst, src) asm volatile("cp.async.cg.shared.global [%0], [%1], 16;" :: "r"(dst), "l"(__cvta_generic_to_global(src)))
#define CP_COMMIT()          asm volatile("cp.async.commit_group;")
#define CP_WAIT(n)           asm volatile("cp.async.wait_group %0;" :: "n"(n))

__device__ __forceinline__ void ldsm4(uint32_t* r, uint32_t a) {
    asm volatile("ldmatrix.sync.aligned.m8n8.x4.shared.b16 {%0,%1,%2,%3}, [%4];"
        : "=r"(r[0]), "=r"(r[1]), "=r"(r[2]), "=r"(r[3]) : "r"(a));
}
__device__ __forceinline__ void ldsm2(uint32_t* r, uint32_t a) {
    asm volatile("ldmatrix.sync.aligned.m8n8.x2.shared.b16 {%0,%1}, [%2];"
        : "=r"(r[0]), "=r"(r[1]) : "r"(a));
}
__device__ __forceinline__ void mma_bf16(float* d, const uint32_t* a, const uint32_t* b) {
    asm volatile("mma.sync.aligned.m16n8k16.row.col.f32.bf16.bf16.f32 "
        "{%0,%1,%2,%3}, {%4,%5,%6,%7}, {%8,%9}, {%0,%1,%2,%3};"
        : "+f"(d[0]), "+f"(d[1]), "+f"(d[2]), "+f"(d[3])
        : "r"(a[0]), "r"(a[1]), "r"(a[2]), "r"(a[3]), "r"(b[0]), "r"(b[1]));
}
__device__ __forceinline__ void split_bf16(float v, bf16& h, bf16& l) {
    h = __float2bfloat16(v);
    l = __float2bfloat16(v - __bfloat162float(h));
}

// ---------------- tile loaders: bf16 global -> SW128 SMEM ----------------
// Tile [128 rows, 64 contraction] bf16, 128B/row, swizzled.
// TR=false: (r,c) = G[(base0+r)*ld + k0 + c]  -> cp.async 16B chunks
// TR=true : (r,c) = G[(k0+c)*ld + base0 + r]  -> LDG.64 + 4x2B STS
template<bool TR>
__device__ __forceinline__ void load_tile(uint32_t sU, char* sc,
    const bf16* __restrict__ G, int ld, int base0, int k0, int tid)
{
    if constexpr (!TR) {
        #pragma unroll
        for (int i = 0; i < 4; i++) {
            int idx = tid + i*256;                  // 1024 chunks of 16B
            int r = idx >> 3, c16 = idx & 7;
            const bf16* src = G + (size_t)(base0 + r)*ld + k0 + c16*8;
            int off = r*128 + c16*16;
            int sw = off ^ ((off >> 3) & 0x70);
            CP_ASYNC16(sU + sw, src);
        }
    } else {
        #pragma unroll
        for (int i = 0; i < 8; i++) {
            int idx = tid + i*256;                  // 2048 loads of 4 bf16
            int c = idx >> 5, r4 = idx & 31;
            uint2 val = *reinterpret_cast<const uint2*>(G + (size_t)(k0 + c)*ld + base0 + r4*4);
            const bf16* vb = reinterpret_cast<const bf16*>(&val);
            #pragma unroll
            for (int j = 0; j < 4; j++) {
                int off = (r4*4 + j)*128 + c*2;
                int sw = off ^ ((off >> 3) & 0x70);
                *reinterpret_cast<bf16*>(sc + sw) = vb[j];
            }
        }
    }
}

// ================= bf16-split warp-MMA GEMM =================
// 128x128 CTA tile, K-tiles of 64, 8 warps 2(m)x4(n), warp 64m x 32n.
// 3-term split: AhiBhi + AhiBlo + AloBhi, fp32 accum.
// EPI 0: (acc + bias[n]) * alpha
// EPI 1: elu(acc + bias[n])
// EPI 2: (elu(acc)+1) * alpha * maskf(row>>3)
// EPI 3: acc (split-K partial)
// EPI 4: acc * dn[(b*S+row)*8+h]
// OUTB: write bf16 hi/lo pair (Ch, Cl) instead of fp32 C.
template<bool ATR, bool BTR, int EPI, int NSPLIT, bool OUTB>
__global__ void __launch_bounds__(256) tgemm(
    const bf16* __restrict__ Ah, const bf16* __restrict__ Al,
    const bf16* __restrict__ Bh, const bf16* __restrict__ Bl,
    float* __restrict__ C, bf16* __restrict__ Ch, bf16* __restrict__ Cl,
    const float* __restrict__ bias, const int* __restrict__ mask,
    const float* __restrict__ dn, float alpha,
    int Kd, int lda, int ldb, int ldc,
    long long sAb, long long sAh2, long long sBb, long long sBh2,
    long long sCb, long long sCh2, long long sCs)
{
    extern __shared__ char dyn[];
    const int ASZ = 128*128;          // 16KB per half tile
    const int BUFSZ = 4*ASZ;          // Ahi, Alo, Bhi, Blo

    uint32_t dynU = smem_u32(dyn);
    uint32_t smU = (dynU + 1023u) & ~1023u;
    char* sm = dyn + (smU - dynU);

    int tid = threadIdx.x;
    int lane = tid & 31, wid = tid >> 5;
    int wm = (wid & 1) * 64, wn = (wid >> 1) * 32;

    int z = blockIdx.z;
    int split = z % NSPLIT, bh = z / NSPLIT;
    int b = bh >> 3, h = bh & 7;
    Ah += (long long)b*sAb + (long long)h*sAh2;
    Al += (long long)b*sAb + (long long)h*sAh2;
    Bh += (long long)b*sBb + (long long)h*sBh2;
    Bl += (long long)b*sBb + (long long)h*sBh2;
    long long coff = (long long)b*sCb + (long long)h*sCh2 + (long long)split*sCs;
    C += coff;
    if (OUTB) { Ch += coff; Cl += coff; }
    int kchunk = Kd / NSPLIT;
    int kbeg = split * kchunk;
    int nk = kchunk / 64;
    int m0 = blockIdx.y * 128, n0 = blockIdx.x * 128;

    float acc[4][4][4] = {};

    auto copy_stage = [&](int buf, int k0) {
        uint32_t dU = smU + buf*BUFSZ;
        char* dc = sm + buf*BUFSZ;
        load_tile<ATR>(dU,         dc,         Ah, lda, m0, k0, tid);
        load_tile<ATR>(dU + ASZ,   dc + ASZ,   Al, lda, m0, k0, tid);
        load_tile<BTR>(dU + 2*ASZ, dc + 2*ASZ, Bh, ldb, n0, k0, tid);
        load_tile<BTR>(dU + 3*ASZ, dc + 3*ASZ, Bl, ldb, n0, k0, tid);
    };

    copy_stage(0, kbeg);
    CP_COMMIT();

    int rA = wm + (lane & 15);
    int rB = wn + (lane & 7);
    int cAbase = lane >> 4;
    int cBbase = (lane >> 3) & 1;

    for (int it = 0; it < nk; it++) {
        int buf = it & 1;
        if (it + 1 < nk) {
            copy_stage(buf ^ 1, kbeg + (it+1)*64);
            CP_COMMIT();
            CP_WAIT(1);
        } else {
            CP_WAIT(0);
        }
        __syncthreads();
        uint32_t aH = smU + buf*BUFSZ;
        uint32_t aL = aH + ASZ;
        uint32_t bH = aH + 2*ASZ;
        uint32_t bL = aH + 3*ASZ;
        #pragma unroll
        for (int ks = 0; ks < 4; ks++) {
            uint32_t afh[4][4], afl[4][4], bfh[4][2], bfl[4][2];
            #pragma unroll
            for (int mi = 0; mi < 4; mi++) {
                int row = rA + mi*16;
                int sw = row*128 + (((ks*2 + cAbase) ^ (row & 7)) * 16);
                ldsm4(afh[mi], aH + sw);
                ldsm4(afl[mi], aL + sw);
            }
            #pragma unroll
            for (int ni = 0; ni < 4; ni++) {
                int row = rB + ni*8;
                int sw = row*128 + (((ks*2 + cBbase) ^ (row & 7)) * 16);
                ldsm2(bfh[ni], bH + sw);
                ldsm2(bfl[ni], bL + sw);
            }
            #pragma unroll
            for (int mi = 0; mi < 4; mi++)
                #pragma unroll
                for (int ni = 0; ni < 4; ni++) {
                    mma_bf16(acc[mi][ni], afh[mi], bfh[ni]);
                    mma_bf16(acc[mi][ni], afh[mi], bfl[ni]);
                    mma_bf16(acc[mi][ni], afl[mi], bfh[ni]);
                }
        }
        __syncthreads();
    }

    // ---------------- epilogue ----------------
    #pragma unroll
    for (int mi = 0; mi < 4; mi++) {
        int r0 = m0 + wm + mi*16 + (lane >> 2);
        int r1 = r0 + 8;
        float f0 = 1.0f, f1 = 1.0f;
        if (EPI == 2) {
            f0 = mask ? (float)mask[r0 >> 3] : 1.0f;
            f1 = mask ? (float)mask[r1 >> 3] : 1.0f;
        } else if (EPI == 4) {
            f0 = dn[((size_t)(b*SS + r0))*8 + h];
            f1 = dn[((size_t)(b*SS + r1))*8 + h];
        }
        #pragma unroll
        for (int ni = 0; ni < 4; ni++) {
            int c0 = n0 + wn + ni*8 + (lane & 3)*2;
            float d0 = acc[mi][ni][0], d1 = acc[mi][ni][1];
            float d2 = acc[mi][ni][2], d3 = acc[mi][ni][3];
            if (EPI == 0) {
                float b0 = bias ? bias[c0] : 0.0f, b1 = bias ? bias[c0+1] : 0.0f;
                d0 = (d0 + b0)*alpha; d1 = (d1 + b1)*alpha;
                d2 = (d2 + b0)*alpha; d3 = (d3 + b1)*alpha;
            } else if (EPI == 1) {
                float b0 = bias[c0], b1 = bias[c0+1];
                d0 += b0; d1 += b1; d2 += b0; d3 += b1;
                d0 = d0 > 0.0f ? d0 : expm1f(d0);
                d1 = d1 > 0.0f ? d1 : expm1f(d1);
                d2 = d2 > 0.0f ? d2 : expm1f(d2);
                d3 = d3 > 0.0f ? d3 : expm1f(d3);
            } else if (EPI == 2) {
                d0 = (d0 > 0.0f ? d0 + 1.0f : expf(d0)) * alpha * f0;
                d1 = (d1 > 0.0f ? d1 + 1.0f : expf(d1)) * alpha * f0;
                d2 = (d2 > 0.0f ? d2 + 1.0f : expf(d2)) * alpha * f1;
                d3 = (d3 > 0.0f ? d3 + 1.0f : expf(d3)) * alpha * f1;
            } else if (EPI == 4) {
                d0 *= f0; d1 *= f0; d2 *= f1; d3 *= f1;
            }
            if (OUTB) {
                bf16 h0, l0, h1, l1, h2, l2, h3, l3;
                split_bf16(d0, h0, l0); split_bf16(d1, h1, l1);
                split_bf16(d2, h2, l2); split_bf16(d3, h3, l3);
                *reinterpret_cast<__nv_bfloat162*>(Ch + (size_t)r0*ldc + c0) = __nv_bfloat162(h0, h1);
                *reinterpret_cast<__nv_bfloat162*>(Cl + (size_t)r0*ldc + c0) = __nv_bfloat162(l0, l1);
                *reinterpret_cast<__nv_bfloat162*>(Ch + (size_t)r1*ldc + c0) = __nv_bfloat162(h2, h3);
                *reinterpret_cast<__nv_bfloat162*>(Cl + (size_t)r1*ldc + c0) = __nv_bfloat162(l2, l3);
            } else {
                *reinterpret_cast<float2*>(C + (size_t)r0*ldc + c0) = make_float2(d0, d1);
                *reinterpret_cast<float2*>(C + (size_t)r1*ldc + c0) = make_float2(d2, d3);
            }
        }
    }
}

// ---------------- converts ----------------
__global__ void conv_kernel(const float* __restrict__ src, bf16* __restrict__ hi,
                            bf16* __restrict__ lo, int n)
{
    int i = blockIdx.x*256 + threadIdx.x;
    if (i < n) { bf16 h, l; split_bf16(src[i], h, l); hi[i] = h; lo[i] = l; }
}
__global__ void convT_kernel(const float* __restrict__ src, bf16* __restrict__ hi,
                             bf16* __restrict__ lo, int R, int C)
{
    int i = blockIdx.x*256 + threadIdx.x;
    if (i < R*C) {
        int r = i / C, c = i % C;
        bf16 h, l; split_bf16(src[i], h, l);
        hi[(size_t)c*R + r] = h; lo[(size_t)c*R + r] = l;
    }
}

// ---------------- LayerNorm ----------------
__global__ void ln_kernel(const float* __restrict__ in1, const float* __restrict__ in2,
                          const int* __restrict__ mask,
                          const float* __restrict__ gamma, const float* __restrict__ beta,
                          float* __restrict__ outf, bf16* __restrict__ outh, bf16* __restrict__ outl)
{
    int row = blockIdx.x;
    int t = threadIdx.x;
    float x = in1[(size_t)row*DD + t];
    if (in2) {
        float mf = mask ? (float)mask[row] : 1.0f;
        x += in2[(size_t)row*DD + t] * mf;
    }
    __shared__ float smv[4];
    float s = x;
    #pragma unroll
    for (int o = 16; o; o >>= 1) s += __shfl_down_sync(0xffffffffu, s, o);
    if ((t & 31) == 0) smv[t >> 5] = s;
    __syncthreads();
    float mu = (smv[0] + smv[1] + smv[2] + smv[3]) * (1.0f/128.0f);
    float d = x - mu;
    float s2 = d * d;
    __syncthreads();
    #pragma unroll
    for (int o = 16; o; o >>= 1) s2 += __shfl_down_sync(0xffffffffu, s2, o);
    if ((t & 31) == 0) smv[t >> 5] = s2;
    __syncthreads();
    float var = (smv[0] + smv[1] + smv[2] + smv[3]) * (1.0f/128.0f);
    float y = d * rsqrtf(var + 1e-3f) * gamma[t] + beta[t];
    size_t idx = (size_t)row*DD + t;
    if (outf) outf[idx] = y;
    if (outh) { bf16 h, l; split_bf16(y, h, l); outh[idx] = h; outl[idx] = l; }
}

// ---------------- split-K reduces ----------------
__global__ void reduce_kv_kernel(const float* __restrict__ part,
                                 bf16* __restrict__ hi, bf16* __restrict__ lo)
{
    size_t i = (size_t)blockIdx.x*256 + threadIdx.x;   // 32 * 32768 total
    size_t bh = i >> 15, off = i & 32767;
    float s = 0.0f;
    #pragma unroll
    for (int sp = 0; sp < 8; sp++) s += part[(bh*8 + sp)*32768 + off];
    bf16 h, l; split_bf16(s, h, l);
    hi[i] = h; lo[i] = l;
}

__global__ void reduce_wo_kernel(const float* __restrict__ part, const float* __restrict__ bias,
                                 float* __restrict__ out)
{
    size_t i = (size_t)blockIdx.x*256 + threadIdx.x;
    float s = bias[i & 127];
    #pragma unroll
    for (int sp = 0; sp < 4; sp++) s += part[(size_t)sp*2097152 + i];
    out[i] = s;
}

// ---------------- ksum (from bf16 hi/lo kp) ----------------
__global__ void ksum_part_kernel(const bf16* __restrict__ kph, const bf16* __restrict__ kpl,
                                 float* __restrict__ part)
{
    int bh = blockIdx.x, ch = blockIdx.y, m = threadIdx.x;
    int b = bh >> 3, h = bh & 7;
    size_t base = (size_t)b*SS*HM + (size_t)h*MM + (size_t)(ch*256)*HM + m;
    float s = 0.0f;
    for (int i = 0; i < 256; i++) {
        size_t a = base + (size_t)i*HM;
        s += __bfloat162float(kph[a]) + __bfloat162float(kpl[a]);
    }
    part[((size_t)bh*16 + ch)*256 + m] = s;
}

__global__ void ksum_reduce_kernel(const float* __restrict__ part, float* __restrict__ ks)
{
    int bh = blockIdx.x, m = threadIdx.x;
    float s = 0.0f;
    #pragma unroll
    for (int c = 0; c < 16; c++) s += part[((size_t)bh*16 + c)*256 + m];
    ks[bh*256 + m] = s;
}

// ---------------- denom (from bf16 hi/lo qp) ----------------
__global__ void denom_kernel(const bf16* __restrict__ qph, const bf16* __restrict__ qpl,
                             const float* __restrict__ ksum, float* __restrict__ denom)
{
    int warp = threadIdx.x >> 5, lane = threadIdx.x & 31;
    int r = blockIdx.x * 8 + warp;
    size_t qb = (size_t)r * MM;
    int b = r / (SS * HH);
    int h = r & 7;
    const float* ks = ksum + (b*HH + h) * MM;
    float s = 0.0f;
    for (int i = lane; i < MM; i += 32) {
        float qv = __bfloat162float(qph[qb + i]) + __bfloat162float(qpl[qb + i]);
        s += qv * ks[i];
    }
    #pragma unroll
    for (int o = 16; o; o >>= 1) s += __shfl_down_sync(0xffffffffu, s, o);
    if (lane == 0) denom[r] = 1.0f / (s + 1e-6f);
}

// ---------------- host-side launch ----------------
template<typename T>
static T* sym_addr(const void* sym)
{
    void* p = nullptr;
    cudaGetSymbolAddress(&p, sym);
    return (T*)p;
}

#define SMEM_REQ (2*4*128*128 + 1024)   // 132096

extern "C" void kernel_launch(void* const* d_in, const int* in_sizes, int n_in,
                              void* d_out, int out_size)
{
    (void)in_sizes; (void)n_in; (void)out_size;
    const float* Q      = (const float*)d_in[0];
    const float* X      = (const float*)d_in[1];
    const int*   mask   = (const int*)  d_in[2];
    const float* Wq     = (const float*)d_in[3];
    const float* bq     = (const float*)d_in[4];
    const float* Wk     = (const float*)d_in[5];
    const float* bk     = (const float*)d_in[6];
    const float* Wv     = (const float*)d_in[7];
    const float* bv     = (const float*)d_in[8];
    const float* Wo     = (const float*)d_in[9];
    const float* bo     = (const float*)d_in[10];
    const float* proj   = (const float*)d_in[11];
    const float* ln1_g  = (const float*)d_in[12];
    const float* ln1_b  = (const float*)d_in[13];
    const float* ln2_g  = (const float*)d_in[14];
    const float* ln2_b  = (const float*)d_in[15];
    const float* fln0_g = (const float*)d_in[16];
    const float* fln0_b = (const float*)d_in[17];
    const float* f_w0   = (const float*)d_in[18];
    const float* f_b0   = (const float*)d_in[19];
    const float* fln1_g = (const float*)d_in[20];
    const float* fln1_b = (const float*)d_in[21];
    const float* f_w1   = (const float*)d_in[22];
    const float* f_b1   = (const float*)d_in[23];
    float* out = (float*)d_out;

    float* Xn   = sym_addr<float>(g_Xn);
    float* part = sym_addr<float>(g_part);
    float* ksp  = sym_addr<float>(g_ksp);
    float* ks   = sym_addr<float>(g_ks);
    float* dn   = sym_addr<float>(g_dn);
    float* ao   = sym_addr<float>(g_ao);
    float* out1 = sym_addr<float>(g_out1);
    float* tB   = sym_addr<float>(g_tB);

    bf16* bQ    = sym_addr<bf16>(b_Q);      bf16* bQl    = bQ    + (size_t)BS*DD;
    bf16* bXn   = sym_addr<bf16>(b_Xn);     bf16* bXnl   = bXn   + (size_t)BS*DD;
    bf16* bWqT  = sym_addr<bf16>(b_WqT);    bf16* bWqTl  = bWqT  + (size_t)HK*DD;
    bf16* bWkT  = sym_addr<bf16>(b_WkT);    bf16* bWkTl  = bWkT  + (size_t)HK*DD;
    bf16* bWvT  = sym_addr<bf16>(b_WvT);    bf16* bWvTl  = bWvT  + (size_t)HK*DD;
    bf16* bWoT  = sym_addr<bf16>(b_WoT);    bf16* bWoTl  = bWoT  + (size_t)DD*HK;
    bf16* bproj = sym_addr<bf16>(b_proj);   bf16* bprojl = bproj + (size_t)MM*KK;
    bf16* bfw0T = sym_addr<bf16>(b_fw0T);   bf16* bfw0Tl = bfw0T + (size_t)DD*DD;
    bf16* bfw1T = sym_addr<bf16>(b_fw1T);   bf16* bfw1Tl = bfw1T + (size_t)DD*DD;
    bf16* bq_h  = sym_addr<bf16>(b_q);      bf16* bq_l   = bq_h  + (size_t)BS*HK;
    bf16* bk_h  = sym_addr<bf16>(b_k);      bf16* bk_l   = bk_h  + (size_t)BS*HK;
    bf16* bv_h  = sym_addr<bf16>(b_v);      bf16* bv_l   = bv_h  + (size_t)BS*HK;
    bf16* bqp_h = sym_addr<bf16>(b_qp);     bf16* bqp_l  = bqp_h + (size_t)BSH*MM;
    bf16* bkp_h = sym_addr<bf16>(b_kp);     bf16* bkp_l  = bkp_h + (size_t)BSH*MM;
    bf16* bkv_h = sym_addr<bf16>(b_kv);     bf16* bkv_l  = bkv_h + (size_t)BB*HH*MM*KK;
    bf16* bat_h = sym_addr<bf16>(b_attn);   bf16* bat_l  = bat_h + (size_t)BS*HK;
    bf16* btA_h = sym_addr<bf16>(b_tA);     bf16* btA_l  = btA_h + (size_t)BS*DD;

    const float scale_q    = 0.08838834764831845f;  // 1/sqrt(128)
    const float inv_sqrt_m = 0.0625f;               // 1/sqrt(256)

    cudaFuncSetAttribute(tgemm<false,false,0,1,true >, cudaFuncAttributeMaxDynamicSharedMemorySize, SMEM_REQ);
    cudaFuncSetAttribute(tgemm<false,false,2,1,true >, cudaFuncAttributeMaxDynamicSharedMemorySize, SMEM_REQ);
    cudaFuncSetAttribute(tgemm<true ,true ,3,8,false>, cudaFuncAttributeMaxDynamicSharedMemorySize, SMEM_REQ);
    cudaFuncSetAttribute(tgemm<false,true ,4,1,true >, cudaFuncAttributeMaxDynamicSharedMemorySize, SMEM_REQ);
    cudaFuncSetAttribute(tgemm<false,false,3,4,false>, cudaFuncAttributeMaxDynamicSharedMemorySize, SMEM_REQ);
    cudaFuncSetAttribute(tgemm<false,false,1,1,false>, cudaFuncAttributeMaxDynamicSharedMemorySize, SMEM_REQ);
    cudaFuncSetAttribute(tgemm<false,false,0,1,false>, cudaFuncAttributeMaxDynamicSharedMemorySize, SMEM_REQ);

    // 0. converts (inputs + weights)
    conv_kernel<<<(BS*DD + 255)/256, 256>>>(Q, bQ, bQl, BS*DD);
    conv_kernel<<<(MM*KK + 255)/256, 256>>>(proj, bproj, bprojl, MM*KK);
    convT_kernel<<<(DD*HK + 255)/256, 256>>>(Wq, bWqT, bWqTl, DD, HK);
    convT_kernel<<<(DD*HK + 255)/256, 256>>>(Wk, bWkT, bWkTl, DD, HK);
    convT_kernel<<<(DD*HK + 255)/256, 256>>>(Wv, bWvT, bWvTl, DD, HK);
    convT_kernel<<<(HK*DD + 255)/256, 256>>>(Wo, bWoT, bWoTl, HK, DD);
    convT_kernel<<<(DD*DD + 255)/256, 256>>>(f_w0, bfw0T, bfw0Tl, DD, DD);
    convT_kernel<<<(DD*DD + 255)/256, 256>>>(f_w1, bfw1T, bfw1Tl, DD, DD);

    // 1. Xn = LN(X; ln1) -> fp32 + bf16
    ln_kernel<<<BS, 128>>>(X, nullptr, nullptr, ln1_g, ln1_b, Xn, bXn, bXnl);

    // 2-4. q/k/v projections -> bf16 hi/lo
    tgemm<false,false,0,1,true><<<dim3(HK/128, BS/128, 1), 256, SMEM_REQ>>>(
        bQ, bQl, bWqT, bWqTl, nullptr, bq_h, bq_l, bq, nullptr, nullptr, scale_q,
        DD, DD, DD, HK, 0,0,0,0, 0,0,0);
    tgemm<false,false,0,1,true><<<dim3(HK/128, BS/128, 1), 256, SMEM_REQ>>>(
        bXn, bXnl, bWkT, bWkTl, nullptr, bk_h, bk_l, bk, nullptr, nullptr, 1.0f,
        DD, DD, DD, HK, 0,0,0,0, 0,0,0);
    tgemm<false,false,0,1,true><<<dim3(HK/128, BS/128, 1), 256, SMEM_REQ>>>(
        bXn, bXnl, bWvT, bWvTl, nullptr, bv_h, bv_l, bv, nullptr, nullptr, 1.0f,
        DD, DD, DD, HK, 0,0,0,0, 0,0,0);

    // 5-6. feature maps -> bf16 hi/lo qp/kp
    tgemm<false,false,2,1,true><<<dim3(MM/128, BSH/128, 1), 256, SMEM_REQ>>>(
        bq_h, bq_l, bproj, bprojl, nullptr, bqp_h, bqp_l, nullptr, nullptr, nullptr, inv_sqrt_m,
        KK, KK, KK, MM, 0,0,0,0, 0,0,0);
    tgemm<false,false,2,1,true><<<dim3(MM/128, BSH/128, 1), 256, SMEM_REQ>>>(
        bk_h, bk_l, bproj, bprojl, nullptr, bkp_h, bkp_l, nullptr, mask, nullptr, inv_sqrt_m,
        KK, KK, KK, MM, 0,0,0,0, 0,0,0);

    // 7. kv: A=kp^T, B=v^T, split-K=8 -> fp32 parts -> bf16 kv
    tgemm<true,true,3,8,false><<<dim3(1, MM/128, 32*8), 256, SMEM_REQ>>>(
        bkp_h, bkp_l, bv_h, bv_l, part, nullptr, nullptr, nullptr, nullptr, nullptr, 1.0f,
        SS, HM, HK, KK,
        (long long)SS*HM, MM, (long long)SS*HK, KK,
        2097152LL, 262144LL, 32768LL);
    reduce_kv_kernel<<<(32*32768)/256, 256>>>(part, bkv_h, bkv_l);

    // 8. ksum
    ksum_part_kernel<<<dim3(32, 16), 256>>>(bkp_h, bkp_l, ksp);
    ksum_reduce_kernel<<<32, 256>>>(ksp, ks);

    // 9. denom
    denom_kernel<<<BSH/8, 256>>>(bqp_h, bqp_l, ks, dn);

    // 10. attn = (qp @ kv) * denom -> bf16 hi/lo
    tgemm<false,true,4,1,true><<<dim3(1, SS/128, 32), 256, SMEM_REQ>>>(
        bqp_h, bqp_l, bkv_h, bkv_l, nullptr, bat_h, bat_l, nullptr, nullptr, dn, 1.0f,
        MM, HM, KK, HK,
        (long long)SS*HM, MM, 262144LL, 32768LL,
        (long long)SS*HK, KK, 0);

    // 11. attn_out = attn @ WoT, split-K=4 -> fp32 parts -> ao
    tgemm<false,false,3,4,false><<<dim3(1, BS/128, 4), 256, SMEM_REQ>>>(
        bat_h, bat_l, bWoT, bWoTl, part, nullptr, nullptr, nullptr, nullptr, nullptr, 1.0f,
        HK, HK, HK, DD, 0,0,0,0, 0,0, 2097152LL);
    reduce_wo_kernel<<<(BS*DD)/256, 256>>>(part, bo, ao);

    // 12. out1 = LN(Xn + ao*mask; ln2) -> fp32
    ln_kernel<<<BS, 128>>>(Xn, ao, mask, ln2_g, ln2_b, out1, nullptr, nullptr);

    // 13-16. FFN
    ln_kernel<<<BS, 128>>>(out1, nullptr, nullptr, fln0_g, fln0_b, nullptr, btA_h, btA_l);
    tgemm<false,false,1,1,false><<<dim3(1, BS/128, 1), 256, SMEM_REQ>>>(
        btA_h, btA_l, bfw0T, bfw0Tl, tB, nullptr, nullptr, f_b0, nullptr, nullptr, 1.0f,
        DD, DD, DD, DD, 0,0,0,0, 0,0,0);
    ln_kernel<<<BS, 128>>>(tB, nullptr, nullptr, fln1_g, fln1_b, nullptr, btA_h, btA_l);
    tgemm<false,false,0,1,false><<<dim3(1, BS/128, 1), 256, SMEM_REQ>>>(
        btA_h, btA_l, bfw1T, bfw1Tl, out, nullptr, nullptr, f_b1, nullptr, nullptr, 1.0f,
        DD, DD, DD, DD, 0,0,0,0, 0,0,0);
}

// round 6
// speedup vs baseline: 3.1566x; 1.4637x over previous
#include <cuda_runtime.h>
#include <cuda_bf16.h>
#include <math.h>
#include <stdint.h>

// Problem constants
#define BB 4
#define SS 4096
#define DD 128
#define HH 8
#define KK 128
#define MM 256

#define BS   (BB*SS)        // 16384
#define BSH  (BB*SS*HH)     // 131072
#define HK   (HH*KK)        // 1024
#define HM   (HH*MM)        // 2048

typedef __nv_bfloat16 bf16;

// -------- scratch (static device globals) --------
__device__ float g_Xn  [BS*DD];
__device__ float g_part[2097152];              // kv split-K partials (32*8*32768/4... 8.4MB)
__device__ float g_ks  [BB*HH*MM];
__device__ float g_dn  [BSH];
__device__ float g_ao  [BS*DD];
__device__ float g_out1[BS*DD];
__device__ float g_tB  [BS*DD];

// bf16 hi/lo pairs (hi at [0], lo at [1])
__device__ bf16 b_Q   [2][BS*DD];
__device__ bf16 b_Xn  [2][BS*DD];
__device__ bf16 b_WqT [2][HK*DD];
__device__ bf16 b_WkT [2][HK*DD];
__device__ bf16 b_WvT [2][HK*DD];
__device__ bf16 b_WoT [2][DD*HK];
__device__ bf16 b_proj[2][MM*KK];
__device__ bf16 b_fw0T[2][DD*DD];
__device__ bf16 b_fw1T[2][DD*DD];
__device__ bf16 b_q   [2][BS*HK];
__device__ bf16 b_k   [2][BS*HK];
__device__ bf16 b_qp  [2][(size_t)BSH*MM];     // [b,s,h,m]
__device__ bf16 b_kpT [2][(size_t)BSH*MM];     // [b,h,m,s]
__device__ bf16 b_vT  [2][BS*HK];              // [b,h,k,s]
__device__ bf16 b_kvT [2][BB*HH*KK*MM];        // [b,h,k,m]
__device__ bf16 b_attn[2][(size_t)BS*HK];      // [b,s,h,k]
__device__ bf16 b_tA  [2][BS*DD];

// ================= asm helpers =================
__device__ __forceinline__ uint32_t smem_u32(const void* p) {
    uint32_t a;
    asm("{ .reg .u64 t; cvta.to.shared.u64 t, %1; cvt.u32.u64 %0, t; }" : "=r"(a) : "l"(p));
    return a;
}
#define CP_ASYNC16(dst, src) asm volatile("cp.async.cg.shared.global [%0], [%1], 16;" :: "r"(dst), "l"(__cvta_generic_to_global(src)))
#define CP_COMMIT()          asm volatile("cp.async.commit_group;")
#define CP_WAIT(n)           asm volatile("cp.async.wait_group %0;" :: "n"(n))

__device__ __forceinline__ void ldsm4(uint32_t* r, uint32_t a) {
    asm volatile("ldmatrix.sync.aligned.m8n8.x4.shared.b16 {%0,%1,%2,%3}, [%4];"
        : "=r"(r[0]), "=r"(r[1]), "=r"(r[2]), "=r"(r[3]) : "r"(a));
}
__device__ __forceinline__ void ldsm2(uint32_t* r, uint32_t a) {
    asm volatile("ldmatrix.sync.aligned.m8n8.x2.shared.b16 {%0,%1}, [%2];"
        : "=r"(r[0]), "=r"(r[1]) : "r"(a));
}
__device__ __forceinline__ void mma_bf16(float* d, const uint32_t* a, const uint32_t* b) {
    asm volatile("mma.sync.aligned.m16n8k16.row.col.f32.bf16.bf16.f32 "
        "{%0,%1,%2,%3}, {%4,%5,%6,%7}, {%8,%9}, {%0,%1,%2,%3};"
        : "+f"(d[0]), "+f"(d[1]), "+f"(d[2]), "+f"(d[3])
        : "r"(a[0]), "r"(a[1]), "r"(a[2]), "r"(a[3]), "r"(b[0]), "r"(b[1]));
}
__device__ __forceinline__ void split_bf16(float v, bf16& h, bf16& l) {
    h = __float2bfloat16(v);
    l = __float2bfloat16(v - __bfloat162float(h));
}

// ---------------- tile loader: bf16 global -> SW128 SMEM (contraction-contiguous) ----------------
// Tile [128 rows, 64 c] bf16, 128B/row, swizzled. 256 threads; 16B cp.async.
__device__ __forceinline__ void load_tile(uint32_t sU,
    const bf16* __restrict__ G, int ld, int base0, int k0, int tid)
{
    #pragma unroll
    for (int i = 0; i < 4; i++) {
        int idx = tid + i*256;                  // 1024 chunks of 16B
        int r = idx >> 3, c16 = idx & 7;
        const bf16* src = G + (size_t)(base0 + r)*ld + k0 + c16*8;
        int off = r*128 + c16*16;
        int sw = off ^ ((off >> 3) & 0x70);
        CP_ASYNC16(sU + sw, src);
    }
}

// ================= bf16-split warp-MMA GEMM, 3-stage cp.async =================
// 128x128 CTA tile, K-tiles of 64, 8 warps 2(m)x4(n), warp 64m x 32n.
// 3-term split: AhiBhi + AhiBlo + AloBhi, fp32 accum.
// EPI 0: (acc + bias[col]) * alpha
// EPI 1: elu(acc + bias[col])
// EPI 2: (elu(acc)+1) * alpha                      (qp)
// EPI 3: acc (split-K partial)
// EPI 4: acc * dn[(b*S+row)*8+h]                   (attn)
// EPI 5: (elu(acc)+1) * alpha * maskf[b*S+col]     (kpT; token = column)
// EPI 6: acc + bias[h*128+row]                     (vT; row bias)
template<int EPI, int NSPLIT, bool OUTB>
__global__ void __launch_bounds__(256) tgemm(
    const bf16* __restrict__ Ah, const bf16* __restrict__ Al,
    const bf16* __restrict__ Bh, const bf16* __restrict__ Bl,
    float* __restrict__ C, bf16* __restrict__ Ch, bf16* __restrict__ Cl,
    const float* __restrict__ bias, const int* __restrict__ mask,
    const float* __restrict__ dn, float alpha,
    int Kd, int lda, int ldb, int ldc,
    long long sAb, long long sAh2, long long sBb, long long sBh2,
    long long sCb, long long sCh2, long long sCs)
{
    extern __shared__ char dyn[];
    const int ASZ = 128*128;          // 16KB per half tile
    const int BUFSZ = 4*ASZ;          // Ahi, Alo, Bhi, Blo = 64KB

    uint32_t dynU = smem_u32(dyn);
    uint32_t smU = (dynU + 1023u) & ~1023u;

    int tid = threadIdx.x;
    int lane = tid & 31, wid = tid >> 5;
    int wm = (wid & 1) * 64, wn = (wid >> 1) * 32;

    int z = blockIdx.z;
    int split = z % NSPLIT, bh = z / NSPLIT;
    int b = bh >> 3, h = bh & 7;
    Ah += (long long)b*sAb + (long long)h*sAh2;
    Al += (long long)b*sAb + (long long)h*sAh2;
    Bh += (long long)b*sBb + (long long)h*sBh2;
    Bl += (long long)b*sBb + (long long)h*sBh2;
    long long coff = (long long)b*sCb + (long long)h*sCh2 + (long long)split*sCs;
    if (OUTB) { Ch += coff; Cl += coff; } else { C += coff; }
    int kchunk = Kd / NSPLIT;
    int kbeg = split * kchunk;
    int nk = kchunk / 64;
    int m0 = blockIdx.y * 128, n0 = blockIdx.x * 128;

    float acc[4][4][4] = {};

    auto copy_stage = [&](int st, int k0) {
        uint32_t dU = smU + st*BUFSZ;
        load_tile(dU,         Ah, lda, m0, k0, tid);
        load_tile(dU + ASZ,   Al, lda, m0, k0, tid);
        load_tile(dU + 2*ASZ, Bh, ldb, n0, k0, tid);
        load_tile(dU + 3*ASZ, Bl, ldb, n0, k0, tid);
    };

    copy_stage(0, kbeg);            CP_COMMIT();
    copy_stage(1, kbeg + 64);       CP_COMMIT();

    int rA = wm + (lane & 15);
    int rB = wn + (lane & 7);
    int cAbase = lane >> 4;
    int cBbase = (lane >> 3) & 1;

    for (int it = 0; it < nk; it++) {
        if (it < nk - 1) { CP_WAIT(1); } else { CP_WAIT(0); }
        __syncthreads();
        if (it + 2 < nk) {
            copy_stage((it + 2) % 3, kbeg + (it+2)*64);
            CP_COMMIT();
        }
        uint32_t aH = smU + (it % 3)*BUFSZ;
        uint32_t aL = aH + ASZ;
        uint32_t bH = aH + 2*ASZ;
        uint32_t bL = aH + 3*ASZ;
        #pragma unroll
        for (int ks = 0; ks < 4; ks++) {
            uint32_t afh[4][4], afl[4][4], bfh[4][2], bfl[4][2];
            #pragma unroll
            for (int mi = 0; mi < 4; mi++) {
                int row = rA + mi*16;
                int sw = row*128 + (((ks*2 + cAbase) ^ (row & 7)) * 16);
                ldsm4(afh[mi], aH + sw);
                ldsm4(afl[mi], aL + sw);
            }
            #pragma unroll
            for (int ni = 0; ni < 4; ni++) {
                int row = rB + ni*8;
                int sw = row*128 + (((ks*2 + cBbase) ^ (row & 7)) * 16);
                ldsm2(bfh[ni], bH + sw);
                ldsm2(bfl[ni], bL + sw);
            }
            #pragma unroll
            for (int mi = 0; mi < 4; mi++)
                #pragma unroll
                for (int ni = 0; ni < 4; ni++) {
                    mma_bf16(acc[mi][ni], afh[mi], bfh[ni]);
                    mma_bf16(acc[mi][ni], afh[mi], bfl[ni]);
                    mma_bf16(acc[mi][ni], afl[mi], bfh[ni]);
                }
        }
        __syncthreads();
    }

    // ---------------- epilogue ----------------
    #pragma unroll
    for (int mi = 0; mi < 4; mi++) {
        int r0 = m0 + wm + mi*16 + (lane >> 2);
        int r1 = r0 + 8;
        float f0 = 1.0f, f1 = 1.0f;               // row factors
        if (EPI == 4) {
            f0 = dn[((size_t)(b*SS + r0))*8 + h];
            f1 = dn[((size_t)(b*SS + r1))*8 + h];
        } else if (EPI == 6) {
            f0 = bias[(h << 7) + r0];
            f1 = bias[(h << 7) + r1];
        }
        #pragma unroll
        for (int ni = 0; ni < 4; ni++) {
            int c0 = n0 + wn + ni*8 + (lane & 3)*2;
            float d0 = acc[mi][ni][0], d1 = acc[mi][ni][1];
            float d2 = acc[mi][ni][2], d3 = acc[mi][ni][3];
            if (EPI == 0) {
                float b0 = bias ? bias[c0] : 0.0f, b1 = bias ? bias[c0+1] : 0.0f;
                d0 = (d0 + b0)*alpha; d1 = (d1 + b1)*alpha;
                d2 = (d2 + b0)*alpha; d3 = (d3 + b1)*alpha;
            } else if (EPI == 1) {
                float b0 = bias[c0], b1 = bias[c0+1];
                d0 += b0; d1 += b1; d2 += b0; d3 += b1;
                d0 = d0 > 0.0f ? d0 : expm1f(d0);
                d1 = d1 > 0.0f ? d1 : expm1f(d1);
                d2 = d2 > 0.0f ? d2 : expm1f(d2);
                d3 = d3 > 0.0f ? d3 : expm1f(d3);
            } else if (EPI == 2) {
                d0 = (d0 > 0.0f ? d0 + 1.0f : expf(d0)) * alpha;
                d1 = (d1 > 0.0f ? d1 + 1.0f : expf(d1)) * alpha;
                d2 = (d2 > 0.0f ? d2 + 1.0f : expf(d2)) * alpha;
                d3 = (d3 > 0.0f ? d3 + 1.0f : expf(d3)) * alpha;
            } else if (EPI == 4) {
                d0 *= f0; d1 *= f0; d2 *= f1; d3 *= f1;
            } else if (EPI == 5) {
                float m0f = (float)mask[b*SS + c0];
                float m1f = (float)mask[b*SS + c0 + 1];
                d0 = (d0 > 0.0f ? d0 + 1.0f : expf(d0)) * alpha * m0f;
                d1 = (d1 > 0.0f ? d1 + 1.0f : expf(d1)) * alpha * m1f;
                d2 = (d2 > 0.0f ? d2 + 1.0f : expf(d2)) * alpha * m0f;
                d3 = (d3 > 0.0f ? d3 + 1.0f : expf(d3)) * alpha * m1f;
            } else if (EPI == 6) {
                d0 += f0; d1 += f0; d2 += f1; d3 += f1;
            }
            if (OUTB) {
                bf16 h0, l0, h1, l1, h2, l2, h3, l3;
                split_bf16(d0, h0, l0); split_bf16(d1, h1, l1);
                split_bf16(d2, h2, l2); split_bf16(d3, h3, l3);
                *reinterpret_cast<__nv_bfloat162*>(Ch + (size_t)r0*ldc + c0) = __nv_bfloat162(h0, h1);
                *reinterpret_cast<__nv_bfloat162*>(Cl + (size_t)r0*ldc + c0) = __nv_bfloat162(l0, l1);
                *reinterpret_cast<__nv_bfloat162*>(Ch + (size_t)r1*ldc + c0) = __nv_bfloat162(h2, h3);
                *reinterpret_cast<__nv_bfloat162*>(Cl + (size_t)r1*ldc + c0) = __nv_bfloat162(l2, l3);
            } else {
                *reinterpret_cast<float2*>(C + (size_t)r0*ldc + c0) = make_float2(d0, d1);
                *reinterpret_cast<float2*>(C + (size_t)r1*ldc + c0) = make_float2(d2, d3);
            }
        }
    }
}

// ---------------- converts ----------------
__global__ void conv_kernel(const float* __restrict__ src, bf16* __restrict__ hi,
                            bf16* __restrict__ lo, int n)
{
    int i = blockIdx.x*256 + threadIdx.x;
    if (i < n) { bf16 h, l; split_bf16(src[i], h, l); hi[i] = h; lo[i] = l; }
}
__global__ void convT_kernel(const float* __restrict__ src, bf16* __restrict__ hi,
                             bf16* __restrict__ lo, int R, int C)
{
    int i = blockIdx.x*256 + threadIdx.x;
    if (i < R*C) {
        int r = i / C, c = i % C;
        bf16 h, l; split_bf16(src[i], h, l);
        hi[(size_t)c*R + r] = h; lo[(size_t)c*R + r] = l;
    }
}

// ---------------- LayerNorm ----------------
__global__ void ln_kernel(const float* __restrict__ in1, const float* __restrict__ in2,
                          const int* __restrict__ mask,
                          const float* __restrict__ gamma, const float* __restrict__ beta,
                          float* __restrict__ outf, bf16* __restrict__ outh, bf16* __restrict__ outl)
{
    int row = blockIdx.x;
    int t = threadIdx.x;
    float x = in1[(size_t)row*DD + t];
    if (in2) {
        float mf = mask ? (float)mask[row] : 1.0f;
        x += in2[(size_t)row*DD + t] * mf;
    }
    __shared__ float smv[4];
    float s = x;
    #pragma unroll
    for (int o = 16; o; o >>= 1) s += __shfl_down_sync(0xffffffffu, s, o);
    if ((t & 31) == 0) smv[t >> 5] = s;
    __syncthreads();
    float mu = (smv[0] + smv[1] + smv[2] + smv[3]) * (1.0f/128.0f);
    float d = x - mu;
    float s2 = d * d;
    __syncthreads();
    #pragma unroll
    for (int o = 16; o; o >>= 1) s2 += __shfl_down_sync(0xffffffffu, s2, o);
    if ((t & 31) == 0) smv[t >> 5] = s2;
    __syncthreads();
    float var = (smv[0] + smv[1] + smv[2] + smv[3]) * (1.0f/128.0f);
    float y = d * rsqrtf(var + 1e-3f) * gamma[t] + beta[t];
    size_t idx = (size_t)row*DD + t;
    if (outf) outf[idx] = y;
    if (outh) { bf16 h, l; split_bf16(y, h, l); outh[idx] = h; outl[idx] = l; }
}

// ---------------- kv reduce + transpose: part[bh][8][m256][k128] -> kvT[bh][k][m] hi/lo ----------------
__global__ void reduce_kvT_kernel(const float* __restrict__ part,
                                  bf16* __restrict__ hi, bf16* __restrict__ lo)
{
    int bh = blockIdx.x;
    int tm = (blockIdx.y >> 1) * 64;     // m tile base (0,64,128,192)
    int tk = (blockIdx.y & 1) * 64;      // k tile base (0,64)
    __shared__ float t[64][65];
    const float* p = part + (size_t)bh*8*32768;
    int tid = threadIdx.x;
    #pragma unroll
    for (int i = 0; i < 16; i++) {
        int idx = tid + i*256;
        int r = idx >> 6, c = idx & 63;          // r = m-local, c = k-local
        float s = 0.0f;
        #pragma unroll
        for (int sp = 0; sp < 8; sp++) s += p[sp*32768 + (tm+r)*128 + tk+c];
        t[c][r] = s;                             // store transposed
    }
    __syncthreads();
    bf16* H = hi + (size_t)bh*KK*MM;
    bf16* L = lo + (size_t)bh*KK*MM;
    #pragma unroll
    for (int i = 0; i < 16; i++) {
        int idx = tid + i*256;
        int kk2 = idx >> 6, mm2 = idx & 63;
        float s = t[kk2][mm2];
        bf16 h, l; split_bf16(s, h, l);
        H[(size_t)(tk+kk2)*MM + tm+mm2] = h;
        L[(size_t)(tk+kk2)*MM + tm+mm2] = l;
    }
}

// ---------------- ksum from kpT: ks[bh,m] = sum_s kpT[bh,m,s] ----------------
__global__ void ksum_kernel(const bf16* __restrict__ kph, const bf16* __restrict__ kpl,
                            float* __restrict__ ks)
{
    int bh = blockIdx.x;
    int wid = threadIdx.x >> 5, lane = threadIdx.x & 31;
    int m = blockIdx.y * 8 + wid;
    const bf16* H = kph + ((size_t)bh*MM + m)*SS;
    const bf16* L = kpl + ((size_t)bh*MM + m)*SS;
    float s = 0.0f;
    for (int i = lane; i < SS; i += 32)
        s += __bfloat162float(H[i]) + __bfloat162float(L[i]);
    #pragma unroll
    for (int o = 16; o; o >>= 1) s += __shfl_down_sync(0xffffffffu, s, o);
    if (lane == 0) ks[bh*MM + m] = s;
}

// ---------------- denom ----------------
__global__ void denom_kernel(const bf16* __restrict__ qph, const bf16* __restrict__ qpl,
                             const float* __restrict__ ksum, float* __restrict__ denom)
{
    int warp = threadIdx.x >> 5, lane = threadIdx.x & 31;
    int r = blockIdx.x * 8 + warp;
    size_t qb = (size_t)r * MM;
    int b = r / (SS * HH);
    int h = r & 7;
    const float* ks = ksum + (b*HH + h) * MM;
    float s = 0.0f;
    for (int i = lane; i < MM; i += 32) {
        float qv = __bfloat162float(qph[qb + i]) + __bfloat162float(qpl[qb + i]);
        s += qv * ks[i];
    }
    #pragma unroll
    for (int o = 16; o; o >>= 1) s += __shfl_down_sync(0xffffffffu, s, o);
    if (lane == 0) denom[r] = 1.0f / (s + 1e-6f);
}

// ---------------- host-side launch ----------------
template<typename T>
static T* sym_addr(const void* sym)
{
    void* p = nullptr;
    cudaGetSymbolAddress(&p, sym);
    return (T*)p;
}

#define SMEM_REQ (3*4*128*128 + 1024)   // 197632

extern "C" void kernel_launch(void* const* d_in, const int* in_sizes, int n_in,
                              void* d_out, int out_size)
{
    (void)in_sizes; (void)n_in; (void)out_size;
    const float* Q      = (const float*)d_in[0];
    const float* X      = (const float*)d_in[1];
    const int*   mask   = (const int*)  d_in[2];
    const float* Wq     = (const float*)d_in[3];
    const float* bq     = (const float*)d_in[4];
    const float* Wk     = (const float*)d_in[5];
    const float* bk     = (const float*)d_in[6];
    const float* Wv     = (const float*)d_in[7];
    const float* bv     = (const float*)d_in[8];
    const float* Wo     = (const float*)d_in[9];
    const float* bo     = (const float*)d_in[10];
    const float* proj   = (const float*)d_in[11];
    const float* ln1_g  = (const float*)d_in[12];
    const float* ln1_b  = (const float*)d_in[13];
    const float* ln2_g  = (const float*)d_in[14];
    const float* ln2_b  = (const float*)d_in[15];
    const float* fln0_g = (const float*)d_in[16];
    const float* fln0_b = (const float*)d_in[17];
    const float* f_w0   = (const float*)d_in[18];
    const float* f_b0   = (const float*)d_in[19];
    const float* fln1_g = (const float*)d_in[20];
    const float* fln1_b = (const float*)d_in[21];
    const float* f_w1   = (const float*)d_in[22];
    const float* f_b1   = (const float*)d_in[23];
    float* out = (float*)d_out;

    float* Xn   = sym_addr<float>(g_Xn);
    float* part = sym_addr<float>(g_part);
    float* ks   = sym_addr<float>(g_ks);
    float* dn   = sym_addr<float>(g_dn);
    float* ao   = sym_addr<float>(g_ao);
    float* out1 = sym_addr<float>(g_out1);
    float* tB   = sym_addr<float>(g_tB);

    bf16* bQ    = sym_addr<bf16>(b_Q);      bf16* bQl    = bQ    + (size_t)BS*DD;
    bf16* bXn   = sym_addr<bf16>(b_Xn);     bf16* bXnl   = bXn   + (size_t)BS*DD;
    bf16* bWqT  = sym_addr<bf16>(b_WqT);    bf16* bWqTl  = bWqT  + (size_t)HK*DD;
    bf16* bWkT  = sym_addr<bf16>(b_WkT);    bf16* bWkTl  = bWkT  + (size_t)HK*DD;
    bf16* bWvT  = sym_addr<bf16>(b_WvT);    bf16* bWvTl  = bWvT  + (size_t)HK*DD;
    bf16* bWoT  = sym_addr<bf16>(b_WoT);    bf16* bWoTl  = bWoT  + (size_t)DD*HK;
    bf16* bproj = sym_addr<bf16>(b_proj);   bf16* bprojl = bproj + (size_t)MM*KK;
    bf16* bfw0T = sym_addr<bf16>(b_fw0T);   bf16* bfw0Tl = bfw0T + (size_t)DD*DD;
    bf16* bfw1T = sym_addr<bf16>(b_fw1T);   bf16* bfw1Tl = bfw1T + (size_t)DD*DD;
    bf16* bq_h  = sym_addr<bf16>(b_q);      bf16* bq_l   = bq_h  + (size_t)BS*HK;
    bf16* bk_h  = sym_addr<bf16>(b_k);      bf16* bk_l   = bk_h  + (size_t)BS*HK;
    bf16* bqp_h = sym_addr<bf16>(b_qp);     bf16* bqp_l  = bqp_h + (size_t)BSH*MM;
    bf16* bkpT_h= sym_addr<bf16>(b_kpT);    bf16* bkpT_l = bkpT_h+ (size_t)BSH*MM;
    bf16* bvT_h = sym_addr<bf16>(b_vT);     bf16* bvT_l  = bvT_h + (size_t)BS*HK;
    bf16* bkvT_h= sym_addr<bf16>(b_kvT);    bf16* bkvT_l = bkvT_h+ (size_t)BB*HH*KK*MM;
    bf16* bat_h = sym_addr<bf16>(b_attn);   bf16* bat_l  = bat_h + (size_t)BS*HK;
    bf16* btA_h = sym_addr<bf16>(b_tA);     bf16* btA_l  = btA_h + (size_t)BS*DD;

    const float scale_q    = 0.08838834764831845f;  // 1/sqrt(128)
    const float inv_sqrt_m = 0.0625f;               // 1/sqrt(256)

    cudaFuncSetAttribute(tgemm<0,1,true >, cudaFuncAttributeMaxDynamicSharedMemorySize, SMEM_REQ);
    cudaFuncSetAttribute(tgemm<2,1,true >, cudaFuncAttributeMaxDynamicSharedMemorySize, SMEM_REQ);
    cudaFuncSetAttribute(tgemm<5,1,true >, cudaFuncAttributeMaxDynamicSharedMemorySize, SMEM_REQ);
    cudaFuncSetAttribute(tgemm<6,1,true >, cudaFuncAttributeMaxDynamicSharedMemorySize, SMEM_REQ);
    cudaFuncSetAttribute(tgemm<3,8,false>, cudaFuncAttributeMaxDynamicSharedMemorySize, SMEM_REQ);
    cudaFuncSetAttribute(tgemm<4,1,true >, cudaFuncAttributeMaxDynamicSharedMemorySize, SMEM_REQ);
    cudaFuncSetAttribute(tgemm<0,1,false>, cudaFuncAttributeMaxDynamicSharedMemorySize, SMEM_REQ);
    cudaFuncSetAttribute(tgemm<1,1,false>, cudaFuncAttributeMaxDynamicSharedMemorySize, SMEM_REQ);

    // 0. converts
    conv_kernel<<<(BS*DD + 255)/256, 256>>>(Q, bQ, bQl, BS*DD);
    conv_kernel<<<(MM*KK + 255)/256, 256>>>(proj, bproj, bprojl, MM*KK);
    convT_kernel<<<(DD*HK + 255)/256, 256>>>(Wq, bWqT, bWqTl, DD, HK);
    convT_kernel<<<(DD*HK + 255)/256, 256>>>(Wk, bWkT, bWkTl, DD, HK);
    convT_kernel<<<(DD*HK + 255)/256, 256>>>(Wv, bWvT, bWvTl, DD, HK);
    convT_kernel<<<(HK*DD + 255)/256, 256>>>(Wo, bWoT, bWoTl, HK, DD);
    convT_kernel<<<(DD*DD + 255)/256, 256>>>(f_w0, bfw0T, bfw0Tl, DD, DD);
    convT_kernel<<<(DD*DD + 255)/256, 256>>>(f_w1, bfw1T, bfw1Tl, DD, DD);

    // 1. Xn = LN(X; ln1)
    ln_kernel<<<BS, 128>>>(X, nullptr, nullptr, ln1_g, ln1_b, Xn, bXn, bXnl);

    // 2-3. q, k projections -> bf16 hi/lo [BS, HK]
    tgemm<0,1,true><<<dim3(HK/128, BS/128, 1), 256, SMEM_REQ>>>(
        bQ, bQl, bWqT, bWqTl, nullptr, bq_h, bq_l, bq, nullptr, nullptr, scale_q,
        DD, DD, DD, HK, 0,0,0,0, 0,0,0);
    tgemm<0,1,true><<<dim3(HK/128, BS/128, 1), 256, SMEM_REQ>>>(
        bXn, bXnl, bWkT, bWkTl, nullptr, bk_h, bk_l, bk, nullptr, nullptr, 1.0f,
        DD, DD, DD, HK, 0,0,0,0, 0,0,0);

    // 4. vT[b,h,k,s] = Wv^T(h) @ Xn^T(b) + bv[h,k]  (all contraction-contiguous)
    tgemm<6,1,true><<<dim3(SS/128, 1, 32), 256, SMEM_REQ>>>(
        bWvT, bWvTl, bXn, bXnl, nullptr, bvT_h, bvT_l, bv, nullptr, nullptr, 1.0f,
        DD, DD, DD, SS,
        0, (long long)KK*DD, (long long)SS*DD, 0,
        (long long)HH*KK*SS, (long long)KK*SS, 0);

    // 5. qp[b,s,h,m] = (elu(q @ proj^T)+1)/sqrt(M)
    tgemm<2,1,true><<<dim3(MM/128, BSH/128, 1), 256, SMEM_REQ>>>(
        bq_h, bq_l, bproj, bprojl, nullptr, bqp_h, bqp_l, nullptr, nullptr, nullptr, inv_sqrt_m,
        KK, KK, KK, MM, 0,0,0,0, 0,0,0);

    // 6. kpT[b,h,m,s] = (elu(proj @ k^T)+1)/sqrt(M) * mask[token=col]
    tgemm<5,1,true><<<dim3(SS/128, MM/128, 32), 256, SMEM_REQ>>>(
        bproj, bprojl, bk_h, bk_l, nullptr, bkpT_h, bkpT_l, nullptr, mask, nullptr, inv_sqrt_m,
        KK, KK, HK, SS,
        0, 0, (long long)SS*HK, KK,
        (long long)HH*MM*SS, (long long)MM*SS, 0);

    // 7. kv partials: A=kpT[m,s], B=vT[k,s], split-K=8 over s
    tgemm<3,8,false><<<dim3(1, MM/128, 32*8), 256, SMEM_REQ>>>(
        bkpT_h, bkpT_l, bvT_h, bvT_l, part, nullptr, nullptr, nullptr, nullptr, nullptr, 1.0f,
        SS, SS, SS, KK,
        (long long)HH*MM*SS, (long long)MM*SS, (long long)HH*KK*SS, (long long)KK*SS,
        2097152LL/8*8, 262144LL, 32768LL);   // sCb=2097152
    reduce_kvT_kernel<<<dim3(32, 8), 256>>>(part, bkvT_h, bkvT_l);

    // 8. ksum from kpT (coalesced row sums)
    ksum_kernel<<<dim3(32, 32), 256>>>(bkpT_h, bkpT_l, ks);

    // 9. denom
    denom_kernel<<<BSH/8, 256>>>(bqp_h, bqp_l, ks, dn);

    // 10. attn[b,s,h,k] = (qp @ kvT^T) * dn  -> bf16 hi/lo
    tgemm<4,1,true><<<dim3(1, SS/128, 32), 256, SMEM_REQ>>>(
        bqp_h, bqp_l, bkvT_h, bkvT_l, nullptr, bat_h, bat_l, nullptr, nullptr, dn, 1.0f,
        MM, HM, MM, HK,
        (long long)SS*HM, MM, (long long)HH*KK*MM, (long long)KK*MM,
        (long long)SS*HK, KK, 0);

    // 11. ao = attn @ WoT + bo  (no split-K: 128 CTAs, K=1024)
    tgemm<0,1,false><<<dim3(1, BS/128, 1), 256, SMEM_REQ>>>(
        bat_h, bat_l, bWoT, bWoTl, ao, nullptr, nullptr, bo, nullptr, nullptr, 1.0f,
        HK, HK, HK, DD, 0,0,0,0, 0,0,0);

    // 12. out1 = LN(Xn + ao*mask; ln2)
    ln_kernel<<<BS, 128>>>(Xn, ao, mask, ln2_g, ln2_b, out1, nullptr, nullptr);

    // 13-16. FFN
    ln_kernel<<<BS, 128>>>(out1, nullptr, nullptr, fln0_g, fln0_b, nullptr, btA_h, btA_l);
    tgemm<1,1,false><<<dim3(1, BS/128, 1), 256, SMEM_REQ>>>(
        btA_h, btA_l, bfw0T, bfw0Tl, tB, nullptr, nullptr, f_b0, nullptr, nullptr, 1.0f,
        DD, DD, DD, DD, 0,0,0,0, 0,0,0);
    ln_kernel<<<BS, 128>>>(tB, nullptr, nullptr, fln1_g, fln1_b, nullptr, btA_h, btA_l);
    tgemm<0,1,false><<<dim3(1, BS/128, 1), 256, SMEM_REQ>>>(
        btA_h, btA_l, bfw1T, bfw1Tl, out, nullptr, nullptr, f_b1, nullptr, nullptr, 1.0f,
        DD, DD, DD, DD, 0,0,0,0, 0,0,0);
}

// round 8
// speedup vs baseline: 3.2383x; 1.0259x over previous
#include <cuda_runtime.h>
#include <cuda_bf16.h>
#include <math.h>
#include <stdint.h>

// Problem constants
#define BB 4
#define SS 4096
#define DD 128
#define HH 8
#define KK 128
#define MM 256

#define BS   (BB*SS)        // 16384
#define BSH  (BB*SS*HH)     // 131072
#define HK   (HH*KK)        // 1024
#define HM   (HH*MM)        // 2048

typedef __nv_bfloat16 bf16;

// -------- scratch (static device globals) --------
__device__ float g_Xn  [BS*DD];
__device__ float g_part[2097152];              // kv split-K partials
__device__ float g_ks  [BB*HH*MM];
__device__ float g_dn  [BSH];
__device__ float g_ao  [BS*DD];
__device__ float g_tB  [BS*DD];

// bf16 hi/lo pairs (hi at [0], lo at [1])
__device__ bf16 b_Q   [2][BS*DD];
__device__ bf16 b_Xn  [2][BS*DD];
__device__ bf16 b_WqT [2][HK*DD];
__device__ bf16 b_WkT [2][HK*DD];
__device__ bf16 b_WvT [2][HK*DD];
__device__ bf16 b_WoT [2][DD*HK];
__device__ bf16 b_proj[2][MM*KK];
__device__ bf16 b_fw0T[2][DD*DD];
__device__ bf16 b_fw1T[2][DD*DD];
__device__ bf16 b_q   [2][BS*HK];
__device__ bf16 b_k   [2][BS*HK];
__device__ bf16 b_qp  [2][(size_t)BSH*MM];     // [b,s,h,m]
__device__ bf16 b_kpT [2][(size_t)BSH*MM];     // [b,h,m,s]
__device__ bf16 b_vT  [2][BS*HK];              // [b,h,k,s]
__device__ bf16 b_kvT [2][BB*HH*KK*MM];        // [b,h,k,m]
__device__ bf16 b_attn[2][(size_t)BS*HK];      // [b,s,h,k]
__device__ bf16 b_tA  [2][BS*DD];

// ================= asm helpers =================
__device__ __forceinline__ uint32_t smem_u32(const void* p) {
    uint32_t a;
    asm("{ .reg .u64 t; cvta.to.shared.u64 t, %1; cvt.u32.u64 %0, t; }" : "=r"(a) : "l"(p));
    return a;
}
#define CP_ASYNC16(dst, src) asm volatile("cp.async.cg.shared.global [%0], [%1], 16;" :: "r"(dst), "l"(__cvta_generic_to_global(src)))
#define CP_COMMIT()          asm volatile("cp.async.commit_group;")
#define CP_WAIT(n)           asm volatile("cp.async.wait_group %0;" :: "n"(n))

__device__ __forceinline__ void ldsm4(uint32_t* r, uint32_t a) {
    asm volatile("ldmatrix.sync.aligned.m8n8.x4.shared.b16 {%0,%1,%2,%3}, [%4];"
        : "=r"(r[0]), "=r"(r[1]), "=r"(r[2]), "=r"(r[3]) : "r"(a));
}
__device__ __forceinline__ void mma_bf16(float* d, const uint32_t* a, const uint32_t* b) {
    asm volatile("mma.sync.aligned.m16n8k16.row.col.f32.bf16.bf16.f32 "
        "{%0,%1,%2,%3}, {%4,%5,%6,%7}, {%8,%9}, {%0,%1,%2,%3};"
        : "+f"(d[0]), "+f"(d[1]), "+f"(d[2]), "+f"(d[3])
        : "r"(a[0]), "r"(a[1]), "r"(a[2]), "r"(a[3]), "r"(b[0]), "r"(b[1]));
}
__device__ __forceinline__ void split_bf16(float v, bf16& h, bf16& l) {
    h = __float2bfloat16(v);
    l = __float2bfloat16(v - __bfloat162float(h));
}

// ---------------- tile loader: bf16 global -> SW128 SMEM ----------------
// Tile [128 rows, 64 c] bf16, 128B/row, swizzled. 512 threads; 16B cp.async.
__device__ __forceinline__ void load_tile(uint32_t sU,
    const bf16* __restrict__ G, int ld, int base0, int k0, int tid)
{
    #pragma unroll
    for (int i = 0; i < 2; i++) {
        int idx = tid + i*512;                  // 1024 chunks of 16B
        int r = idx >> 3, c16 = idx & 7;
        const bf16* src = G + (size_t)(base0 + r)*ld + k0 + c16*8;
        int off = r*128 + c16*16;
        int sw = off ^ ((off >> 3) & 0x70);
        CP_ASYNC16(sU + sw, src);
    }
}

// ================= bf16-split warp-MMA GEMM, 3-stage cp.async, 512 threads =================
// 128x128 CTA tile, K-tiles of 64, 16 warps 4(m)x4(n), warp tile 32m x 32n.
// 3-term split: AhiBhi + AhiBlo + AloBhi, fp32 accum.
// EPI 0: (acc + bias[col]) * alpha
// EPI 1: elu(acc + bias[col])
// EPI 2: (elu(acc)+1) * alpha                      (qp)
// EPI 3: acc (split-K partial)
// EPI 4: acc * dn[(b*S+row)*8+h]                   (attn)
// EPI 5: (elu(acc)+1) * alpha * maskf[b*S+col]     (kpT; token = column)
// EPI 6: acc + bias[h*128+row]                     (vT; row bias)
template<int EPI, int NSPLIT, bool OUTB>
__global__ void __launch_bounds__(512) tgemm(
    const bf16* __restrict__ Ah, const bf16* __restrict__ Al,
    const bf16* __restrict__ Bh, const bf16* __restrict__ Bl,
    float* __restrict__ C, bf16* __restrict__ Ch, bf16* __restrict__ Cl,
    const float* __restrict__ bias, const int* __restrict__ mask,
    const float* __restrict__ dn, float alpha,
    int Kd, int lda, int ldb, int ldc,
    long long sAb, long long sAh2, long long sBb, long long sBh2,
    long long sCb, long long sCh2, long long sCs)
{
    extern __shared__ char dyn[];
    const int ASZ = 128*128;          // 16KB per half tile
    const int BUFSZ = 4*ASZ;          // Ahi, Alo, Bhi, Blo = 64KB

    uint32_t dynU = smem_u32(dyn);
    uint32_t smU = (dynU + 1023u) & ~1023u;

    int tid = threadIdx.x;
    int lane = tid & 31, wid = tid >> 5;
    int wm = (wid & 3) * 32, wn = (wid >> 2) * 32;

    int z = blockIdx.z;
    int split = z % NSPLIT, bh = z / NSPLIT;
    int b = bh >> 3, h = bh & 7;
    Ah += (long long)b*sAb + (long long)h*sAh2;
    Al += (long long)b*sAb + (long long)h*sAh2;
    Bh += (long long)b*sBb + (long long)h*sBh2;
    Bl += (long long)b*sBb + (long long)h*sBh2;
    long long coff = (long long)b*sCb + (long long)h*sCh2 + (long long)split*sCs;
    if (OUTB) { Ch += coff; Cl += coff; } else { C += coff; }
    int kchunk = Kd / NSPLIT;
    int kbeg = split * kchunk;
    int nk = kchunk / 64;
    int m0 = blockIdx.y * 128, n0 = blockIdx.x * 128;

    float acc[2][4][4] = {};

    auto copy_stage = [&](int st, int k0) {
        uint32_t dU = smU + st*BUFSZ;
        load_tile(dU,         Ah, lda, m0, k0, tid);
        load_tile(dU + ASZ,   Al, lda, m0, k0, tid);
        load_tile(dU + 2*ASZ, Bh, ldb, n0, k0, tid);
        load_tile(dU + 3*ASZ, Bl, ldb, n0, k0, tid);
    };

    copy_stage(0, kbeg);            CP_COMMIT();
    copy_stage(1, kbeg + 64);       CP_COMMIT();

    // A ldsm.x4: lanes 0-15 -> 16 rows at chunk ks*2, lanes 16-31 -> same rows chunk ks*2+1
    int rA = wm + (lane & 15);
    int cA = lane >> 4;
    // B ldsm.x4: matrices (n0-7,k0-7),(n0-7,k8-15),(n8-15,k0-7),(n8-15,k8-15)
    int rB = wn + (lane & 7) + ((lane >> 4) & 1) * 8;
    int cB = (lane >> 3) & 1;

    for (int it = 0; it < nk; it++) {
        if (it < nk - 1) { CP_WAIT(1); } else { CP_WAIT(0); }
        __syncthreads();
        if (it + 2 < nk) {
            copy_stage((it + 2) % 3, kbeg + (it+2)*64);
            CP_COMMIT();
        }
        uint32_t aH = smU + (it % 3)*BUFSZ;
        uint32_t aL = aH + ASZ;
        uint32_t bH = aH + 2*ASZ;
        uint32_t bL = aH + 3*ASZ;
        #pragma unroll
        for (int ks = 0; ks < 4; ks++) {
            uint32_t afh[2][4], afl[2][4], bfh[4][2], bfl[4][2];
            #pragma unroll
            for (int mi = 0; mi < 2; mi++) {
                int row = rA + mi*16;
                int sw = row*128 + (((ks*2 + cA) ^ (row & 7)) * 16);
                ldsm4(afh[mi], aH + sw);
                ldsm4(afl[mi], aL + sw);
            }
            #pragma unroll
            for (int nj = 0; nj < 2; nj++) {
                int row = rB + nj*16;
                int sw = row*128 + (((ks*2 + cB) ^ (row & 7)) * 16);
                ldsm4(&bfh[nj*2][0], bH + sw);
                ldsm4(&bfl[nj*2][0], bL + sw);
            }
            #pragma unroll
            for (int mi = 0; mi < 2; mi++)
                #pragma unroll
                for (int ni = 0; ni < 4; ni++) {
                    mma_bf16(acc[mi][ni], afh[mi], bfh[ni]);
                    mma_bf16(acc[mi][ni], afh[mi], bfl[ni]);
                    mma_bf16(acc[mi][ni], afl[mi], bfh[ni]);
                }
        }
        __syncthreads();
    }

    // ---------------- epilogue ----------------
    #pragma unroll
    for (int mi = 0; mi < 2; mi++) {
        int r0 = m0 + wm + mi*16 + (lane >> 2);
        int r1 = r0 + 8;
        float f0 = 1.0f, f1 = 1.0f;               // row factors
        if (EPI == 4) {
            f0 = dn[((size_t)(b*SS + r0))*8 + h];
            f1 = dn[((size_t)(b*SS + r1))*8 + h];
        } else if (EPI == 6) {
            f0 = bias[(h << 7) + r0];
            f1 = bias[(h << 7) + r1];
        }
        #pragma unroll
        for (int ni = 0; ni < 4; ni++) {
            int c0 = n0 + wn + ni*8 + (lane & 3)*2;
            float d0 = acc[mi][ni][0], d1 = acc[mi][ni][1];
            float d2 = acc[mi][ni][2], d3 = acc[mi][ni][3];
            if (EPI == 0) {
                float b0 = bias ? bias[c0] : 0.0f, b1 = bias ? bias[c0+1] : 0.0f;
                d0 = (d0 + b0)*alpha; d1 = (d1 + b1)*alpha;
                d2 = (d2 + b0)*alpha; d3 = (d3 + b1)*alpha;
            } else if (EPI == 1) {
                float b0 = bias[c0], b1 = bias[c0+1];
                d0 += b0; d1 += b1; d2 += b0; d3 += b1;
                d0 = d0 > 0.0f ? d0 : expm1f(d0);
                d1 = d1 > 0.0f ? d1 : expm1f(d1);
                d2 = d2 > 0.0f ? d2 : expm1f(d2);
                d3 = d3 > 0.0f ? d3 : expm1f(d3);
            } else if (EPI == 2) {
                d0 = (d0 > 0.0f ? d0 + 1.0f : expf(d0)) * alpha;
                d1 = (d1 > 0.0f ? d1 + 1.0f : expf(d1)) * alpha;
                d2 = (d2 > 0.0f ? d2 + 1.0f : expf(d2)) * alpha;
                d3 = (d3 > 0.0f ? d3 + 1.0f : expf(d3)) * alpha;
            } else if (EPI == 4) {
                d0 *= f0; d1 *= f0; d2 *= f1; d3 *= f1;
            } else if (EPI == 5) {
                float m0f = (float)mask[b*SS + c0];
                float m1f = (float)mask[b*SS + c0 + 1];
                d0 = (d0 > 0.0f ? d0 + 1.0f : expf(d0)) * alpha * m0f;
                d1 = (d1 > 0.0f ? d1 + 1.0f : expf(d1)) * alpha * m1f;
                d2 = (d2 > 0.0f ? d2 + 1.0f : expf(d2)) * alpha * m0f;
                d3 = (d3 > 0.0f ? d3 + 1.0f : expf(d3)) * alpha * m1f;
            } else if (EPI == 6) {
                d0 += f0; d1 += f0; d2 += f1; d3 += f1;
            }
            if (OUTB) {
                bf16 h0, l0, h1, l1, h2, l2, h3, l3;
                split_bf16(d0, h0, l0); split_bf16(d1, h1, l1);
                split_bf16(d2, h2, l2); split_bf16(d3, h3, l3);
                *reinterpret_cast<__nv_bfloat162*>(Ch + (size_t)r0*ldc + c0) = __nv_bfloat162(h0, h1);
                *reinterpret_cast<__nv_bfloat162*>(Cl + (size_t)r0*ldc + c0) = __nv_bfloat162(l0, l1);
                *reinterpret_cast<__nv_bfloat162*>(Ch + (size_t)r1*ldc + c0) = __nv_bfloat162(h2, h3);
                *reinterpret_cast<__nv_bfloat162*>(Cl + (size_t)r1*ldc + c0) = __nv_bfloat162(l2, l3);
            } else {
                *reinterpret_cast<float2*>(C + (size_t)r0*ldc + c0) = make_float2(d0, d1);
                *reinterpret_cast<float2*>(C + (size_t)r1*ldc + c0) = make_float2(d2, d3);
            }
        }
    }
}

// ---------------- converts ----------------
__global__ void conv_kernel(const float* __restrict__ src, bf16* __restrict__ hi,
                            bf16* __restrict__ lo, int n)
{
    int i = blockIdx.x*256 + threadIdx.x;
    if (i < n) { bf16 h, l; split_bf16(src[i], h, l); hi[i] = h; lo[i] = l; }
}
__global__ void convT_kernel(const float* __restrict__ src, bf16* __restrict__ hi,
                             bf16* __restrict__ lo, int R, int C)
{
    int i = blockIdx.x*256 + threadIdx.x;
    if (i < R*C) {
        int r = i / C, c = i % C;
        bf16 h, l; split_bf16(src[i], h, l);
        hi[(size_t)c*R + r] = h; lo[(size_t)c*R + r] = l;
    }
}

// ---------------- LayerNorm helpers ----------------
__device__ __forceinline__ float block_ln(float x, int t, float* smv, float eps,
                                          const float* g, const float* b2)
{
    float s = x;
    #pragma unroll
    for (int o = 16; o; o >>= 1) s += __shfl_down_sync(0xffffffffu, s, o);
    if ((t & 31) == 0) smv[t >> 5] = s;
    __syncthreads();
    float mu = (smv[0] + smv[1] + smv[2] + smv[3]) * (1.0f/128.0f);
    float d = x - mu;
    float s2 = d * d;
    __syncthreads();
    #pragma unroll
    for (int o = 16; o; o >>= 1) s2 += __shfl_down_sync(0xffffffffu, s2, o);
    if ((t & 31) == 0) smv[t >> 5] = s2;
    __syncthreads();
    float var = (smv[0] + smv[1] + smv[2] + smv[3]) * (1.0f/128.0f);
    __syncthreads();
    return d * rsqrtf(var + eps) * g[t] + b2[t];
}

__global__ void ln_kernel(const float* __restrict__ in1,
                          const float* __restrict__ gamma, const float* __restrict__ beta,
                          float* __restrict__ outf, bf16* __restrict__ outh, bf16* __restrict__ outl)
{
    int row = blockIdx.x;
    int t = threadIdx.x;
    __shared__ float smv[4];
    float x = in1[(size_t)row*DD + t];
    float y = block_ln(x, t, smv, 1e-3f, gamma, beta);
    size_t idx = (size_t)row*DD + t;
    if (outf) outf[idx] = y;
    if (outh) { bf16 h, l; split_bf16(y, h, l); outh[idx] = h; outl[idx] = l; }
}

// fused: y1 = LN(Xn + ao*mask; g2) ; y2 = LN(y1; g0) -> bf16 hi/lo only
__global__ void ln_double_kernel(const float* __restrict__ Xn, const float* __restrict__ ao,
                                 const int* __restrict__ mask,
                                 const float* __restrict__ g2, const float* __restrict__ b2,
                                 const float* __restrict__ g0, const float* __restrict__ b0,
                                 bf16* __restrict__ outh, bf16* __restrict__ outl)
{
    int row = blockIdx.x;
    int t = threadIdx.x;
    __shared__ float smv[4];
    float mf = (float)mask[row];
    float x = Xn[(size_t)row*DD + t] + ao[(size_t)row*DD + t] * mf;
    float y1 = block_ln(x, t, smv, 1e-3f, g2, b2);
    float y2 = block_ln(y1, t, smv, 1e-3f, g0, b0);
    size_t idx = (size_t)row*DD + t;
    bf16 h, l; split_bf16(y2, h, l);
    outh[idx] = h; outl[idx] = l;
}

// ---------------- kv reduce + transpose: part[bh][8][m256][k128] -> kvT[bh][k][m] ----------------
__global__ void reduce_kvT_kernel(const float* __restrict__ part,
                                  bf16* __restrict__ hi, bf16* __restrict__ lo)
{
    int bh = blockIdx.x;
    int tm = (blockIdx.y >> 1) * 64;
    int tk = (blockIdx.y & 1) * 64;
    __shared__ float t[64][65];
    const float* p = part + (size_t)bh*8*32768;
    int tid = threadIdx.x;
    #pragma unroll
    for (int i = 0; i < 16; i++) {
        int idx = tid + i*256;
        int r = idx >> 6, c = idx & 63;
        float s = 0.0f;
        #pragma unroll
        for (int sp = 0; sp < 8; sp++) s += p[sp*32768 + (tm+r)*128 + tk+c];
        t[c][r] = s;
    }
    __syncthreads();
    bf16* H = hi + (size_t)bh*KK*MM;
    bf16* L = lo + (size_t)bh*KK*MM;
    #pragma unroll
    for (int i = 0; i < 16; i++) {
        int idx = tid + i*256;
        int kk2 = idx >> 6, mm2 = idx & 63;
        float s = t[kk2][mm2];
        bf16 h, l; split_bf16(s, h, l);
        H[(size_t)(tk+kk2)*MM + tm+mm2] = h;
        L[(size_t)(tk+kk2)*MM + tm+mm2] = l;
    }
}

// ---------------- ksum from kpT ----------------
__global__ void ksum_kernel(const bf16* __restrict__ kph, const bf16* __restrict__ kpl,
                            float* __restrict__ ks)
{
    int bh = blockIdx.x;
    int wid = threadIdx.x >> 5, lane = threadIdx.x & 31;
    int m = blockIdx.y * 8 + wid;
    const bf16* H = kph + ((size_t)bh*MM + m)*SS;
    const bf16* L = kpl + ((size_t)bh*MM + m)*SS;
    float s = 0.0f;
    for (int i = lane; i < SS; i += 32)
        s += __bfloat162float(H[i]) + __bfloat162float(L[i]);
    #pragma unroll
    for (int o = 16; o; o >>= 1) s += __shfl_down_sync(0xffffffffu, s, o);
    if (lane == 0) ks[bh*MM + m] = s;
}

// ---------------- denom ----------------
__global__ void denom_kernel(const bf16* __restrict__ qph, const bf16* __restrict__ qpl,
                             const float* __restrict__ ksum, float* __restrict__ denom)
{
    int warp = threadIdx.x >> 5, lane = threadIdx.x & 31;
    int r = blockIdx.x * 8 + warp;
    size_t qb = (size_t)r * MM;
    int b = r / (SS * HH);
    int h = r & 7;
    const float* ks = ksum + (b*HH + h) * MM;
    float s = 0.0f;
    for (int i = lane; i < MM; i += 32) {
        float qv = __bfloat162float(qph[qb + i]) + __bfloat162float(qpl[qb + i]);
        s += qv * ks[i];
    }
    #pragma unroll
    for (int o = 16; o; o >>= 1) s += __shfl_down_sync(0xffffffffu, s, o);
    if (lane == 0) denom[r] = 1.0f / (s + 1e-6f);
}

// ---------------- host-side launch ----------------
template<typename T>
static T* sym_addr(const void* sym)
{
    void* p = nullptr;
    cudaGetSymbolAddress(&p, sym);
    return (T*)p;
}

#define SMEM_REQ (3*4*128*128 + 1024)   // 197632

extern "C" void kernel_launch(void* const* d_in, const int* in_sizes, int n_in,
                              void* d_out, int out_size)
{
    (void)in_sizes; (void)n_in; (void)out_size;
    const float* Q      = (const float*)d_in[0];
    const float* X      = (const float*)d_in[1];
    const int*   mask   = (const int*)  d_in[2];
    const float* Wq     = (const float*)d_in[3];
    const float* bq     = (const float*)d_in[4];
    const float* Wk     = (const float*)d_in[5];
    const float* bk     = (const float*)d_in[6];
    const float* Wv     = (const float*)d_in[7];
    const float* bv     = (const float*)d_in[8];
    const float* Wo     = (const float*)d_in[9];
    const float* bo     = (const float*)d_in[10];
    const float* proj   = (const float*)d_in[11];
    const float* ln1_g  = (const float*)d_in[12];
    const float* ln1_b  = (const float*)d_in[13];
    const float* ln2_g  = (const float*)d_in[14];
    const float* ln2_b  = (const float*)d_in[15];
    const float* fln0_g = (const float*)d_in[16];
    const float* fln0_b = (const float*)d_in[17];
    const float* f_w0   = (const float*)d_in[18];
    const float* f_b0   = (const float*)d_in[19];
    const float* fln1_g = (const float*)d_in[20];
    const float* fln1_b = (const float*)d_in[21];
    const float* f_w1   = (const float*)d_in[22];
    const float* f_b1   = (const float*)d_in[23];
    float* out = (float*)d_out;

    float* Xn   = sym_addr<float>(g_Xn);
    float* part = sym_addr<float>(g_part);
    float* ks   = sym_addr<float>(g_ks);
    float* dn   = sym_addr<float>(g_dn);
    float* ao   = sym_addr<float>(g_ao);
    float* tB   = sym_addr<float>(g_tB);

    bf16* bQ    = sym_addr<bf16>(b_Q);      bf16* bQl    = bQ    + (size_t)BS*DD;
    bf16* bXn   = sym_addr<bf16>(b_Xn);     bf16* bXnl   = bXn   + (size_t)BS*DD;
    bf16* bWqT  = sym_addr<bf16>(b_WqT);    bf16* bWqTl  = bWqT  + (size_t)HK*DD;
    bf16* bWkT  = sym_addr<bf16>(b_WkT);    bf16* bWkTl  = bWkT  + (size_t)HK*DD;
    bf16* bWvT  = sym_addr<bf16>(b_WvT);    bf16* bWvTl  = bWvT  + (size_t)HK*DD;
    bf16* bWoT  = sym_addr<bf16>(b_WoT);    bf16* bWoTl  = bWoT  + (size_t)DD*HK;
    bf16* bproj = sym_addr<bf16>(b_proj);   bf16* bprojl = bproj + (size_t)MM*KK;
    bf16* bfw0T = sym_addr<bf16>(b_fw0T);   bf16* bfw0Tl = bfw0T + (size_t)DD*DD;
    bf16* bfw1T = sym_addr<bf16>(b_fw1T);   bf16* bfw1Tl = bfw1T + (size_t)DD*DD;
    bf16* bq_h  = sym_addr<bf16>(b_q);      bf16* bq_l   = bq_h  + (size_t)BS*HK;
    bf16* bk_h  = sym_addr<bf16>(b_k);      bf16* bk_l   = bk_h  + (size_t)BS*HK;
    bf16* bqp_h = sym_addr<bf16>(b_qp);     bf16* bqp_l  = bqp_h + (size_t)BSH*MM;
    bf16* bkpT_h= sym_addr<bf16>(b_kpT);    bf16* bkpT_l = bkpT_h+ (size_t)BSH*MM;
    bf16* bvT_h = sym_addr<bf16>(b_vT);     bf16* bvT_l  = bvT_h + (size_t)BS*HK;
    bf16* bkvT_h= sym_addr<bf16>(b_kvT);    bf16* bkvT_l = bkvT_h+ (size_t)BB*HH*KK*MM;
    bf16* bat_h = sym_addr<bf16>(b_attn);   bf16* bat_l  = bat_h + (size_t)BS*HK;
    bf16* btA_h = sym_addr<bf16>(b_tA);     bf16* btA_l  = btA_h + (size_t)BS*DD;

    const float scale_q    = 0.08838834764831845f;  // 1/sqrt(128)
    const float inv_sqrt_m = 0.0625f;               // 1/sqrt(256)

    cudaFuncSetAttribute(tgemm<0,1,true >, cudaFuncAttributeMaxDynamicSharedMemorySize, SMEM_REQ);
    cudaFuncSetAttribute(tgemm<2,1,true >, cudaFuncAttributeMaxDynamicSharedMemorySize, SMEM_REQ);
    cudaFuncSetAttribute(tgemm<5,1,true >, cudaFuncAttributeMaxDynamicSharedMemorySize, SMEM_REQ);
    cudaFuncSetAttribute(tgemm<6,1,true >, cudaFuncAttributeMaxDynamicSharedMemorySize, SMEM_REQ);
    cudaFuncSetAttribute(tgemm<3,8,false>, cudaFuncAttributeMaxDynamicSharedMemorySize, SMEM_REQ);
    cudaFuncSetAttribute(tgemm<4,1,true >, cudaFuncAttributeMaxDynamicSharedMemorySize, SMEM_REQ);
    cudaFuncSetAttribute(tgemm<0,1,false>, cudaFuncAttributeMaxDynamicSharedMemorySize, SMEM_REQ);
    cudaFuncSetAttribute(tgemm<1,1,false>, cudaFuncAttributeMaxDynamicSharedMemorySize, SMEM_REQ);

    // 0. converts
    conv_kernel<<<(BS*DD + 255)/256, 256>>>(Q, bQ, bQl, BS*DD);
    conv_kernel<<<(MM*KK + 255)/256, 256>>>(proj, bproj, bprojl, MM*KK);
    convT_kernel<<<(DD*HK + 255)/256, 256>>>(Wq, bWqT, bWqTl, DD, HK);
    convT_kernel<<<(DD*HK + 255)/256, 256>>>(Wk, bWkT, bWkTl, DD, HK);
    convT_kernel<<<(DD*HK + 255)/256, 256>>>(Wv, bWvT, bWvTl, DD, HK);
    convT_kernel<<<(HK*DD + 255)/256, 256>>>(Wo, bWoT, bWoTl, HK, DD);
    convT_kernel<<<(DD*DD + 255)/256, 256>>>(f_w0, bfw0T, bfw0Tl, DD, DD);
    convT_kernel<<<(DD*DD + 255)/256, 256>>>(f_w1, bfw1T, bfw1Tl, DD, DD);

    // 1. Xn = LN(X; ln1)
    ln_kernel<<<BS, 128>>>(X, ln1_g, ln1_b, Xn, bXn, bXnl);

    // 2-3. q, k projections -> bf16 hi/lo [BS, HK]
    tgemm<0,1,true><<<dim3(HK/128, BS/128, 1), 512, SMEM_REQ>>>(
        bQ, bQl, bWqT, bWqTl, nullptr, bq_h, bq_l, bq, nullptr, nullptr, scale_q,
        DD, DD, DD, HK, 0,0,0,0, 0,0,0);
    tgemm<0,1,true><<<dim3(HK/128, BS/128, 1), 512, SMEM_REQ>>>(
        bXn, bXnl, bWkT, bWkTl, nullptr, bk_h, bk_l, bk, nullptr, nullptr, 1.0f,
        DD, DD, DD, HK, 0,0,0,0, 0,0,0);

    // 4. vT[b,h,k,s] = Wv^T(h) @ Xn^T(b) + bv[h,k]
    tgemm<6,1,true><<<dim3(SS/128, 1, 32), 512, SMEM_REQ>>>(
        bWvT, bWvTl, bXn, bXnl, nullptr, bvT_h, bvT_l, bv, nullptr, nullptr, 1.0f,
        DD, DD, DD, SS,
        0, (long long)KK*DD, (long long)SS*DD, 0,
        (long long)HH*KK*SS, (long long)KK*SS, 0);

    // 5. qp[b,s,h,m] = (elu(q @ proj^T)+1)/sqrt(M)
    tgemm<2,1,true><<<dim3(MM/128, BSH/128, 1), 512, SMEM_REQ>>>(
        bq_h, bq_l, bproj, bprojl, nullptr, bqp_h, bqp_l, nullptr, nullptr, nullptr, inv_sqrt_m,
        KK, KK, KK, MM, 0,0,0,0, 0,0,0);

    // 6. kpT[b,h,m,s] = (elu(proj @ k^T)+1)/sqrt(M) * mask[token=col]
    tgemm<5,1,true><<<dim3(SS/128, MM/128, 32), 512, SMEM_REQ>>>(
        bproj, bprojl, bk_h, bk_l, nullptr, bkpT_h, bkpT_l, nullptr, mask, nullptr, inv_sqrt_m,
        KK, KK, HK, SS,
        0, 0, (long long)SS*HK, KK,
        (long long)HH*MM*SS, (long long)MM*SS, 0);

    // 7. kv partials: A=kpT[m,s], B=vT[k,s], split-K=8 over s
    tgemm<3,8,false><<<dim3(1, MM/128, 32*8), 512, SMEM_REQ>>>(
        bkpT_h, bkpT_l, bvT_h, bvT_l, part, nullptr, nullptr, nullptr, nullptr, nullptr, 1.0f,
        SS, SS, SS, KK,
        (long long)HH*MM*SS, (long long)MM*SS, (long long)HH*KK*SS, (long long)KK*SS,
        2097152LL, 262144LL, 32768LL);
    reduce_kvT_kernel<<<dim3(32, 8), 256>>>(part, bkvT_h, bkvT_l);

    // 8. ksum from kpT
    ksum_kernel<<<dim3(32, 32), 256>>>(bkpT_h, bkpT_l, ks);

    // 9. denom
    denom_kernel<<<BSH/8, 256>>>(bqp_h, bqp_l, ks, dn);

    // 10. attn[b,s,h,k] = (qp @ kvT^T) * dn
    tgemm<4,1,true><<<dim3(1, SS/128, 32), 512, SMEM_REQ>>>(
        bqp_h, bqp_l, bkvT_h, bkvT_l, nullptr, bat_h, bat_l, nullptr, nullptr, dn, 1.0f,
        MM, HM, MM, HK,
        (long long)SS*HM, MM, (long long)HH*KK*MM, (long long)KK*MM,
        (long long)SS*HK, KK, 0);

    // 11. ao = attn @ WoT + bo
    tgemm<0,1,false><<<dim3(1, BS/128, 1), 512, SMEM_REQ>>>(
        bat_h, bat_l, bWoT, bWoTl, ao, nullptr, nullptr, bo, nullptr, nullptr, 1.0f,
        HK, HK, HK, DD, 0,0,0,0, 0,0,0);

    // 12+13. fused: out1 = LN(Xn+ao*mask; ln2); tA = LN(out1; fln0) -> bf16
    ln_double_kernel<<<BS, 128>>>(Xn, ao, mask, ln2_g, ln2_b, fln0_g, fln0_b, btA_h, btA_l);

    // 14-16. FFN
    tgemm<1,1,false><<<dim3(1, BS/128, 1), 512, SMEM_REQ>>>(
        btA_h, btA_l, bfw0T, bfw0Tl, tB, nullptr, nullptr, f_b0, nullptr, nullptr, 1.0f,
        DD, DD, DD, DD, 0,0,0,0, 0,0,0);
    ln_kernel<<<BS, 128>>>(tB, fln1_g, fln1_b, nullptr, btA_h, btA_l);
    tgemm<0,1,false><<<dim3(1, BS/128, 1), 512, SMEM_REQ>>>(
        btA_h, btA_l, bfw1T, bfw1Tl, out, nullptr, nullptr, f_b1, nullptr, nullptr, 1.0f,
        DD, DD, DD, DD, 0,0,0,0, 0,0,0);
}